// round 1
// baseline (speedup 1.0000x reference)
#include <cuda_runtime.h>
#include <cstdint>

#define NMAX 10000
#define D 256

// ---------------- scratch (no allocation allowed) ----------------
__device__ float g_xl[NMAX * D];
__device__ float g_xr[NMAX * D];
__device__ float g_agg[NMAX * D];
__device__ float g_denom[NMAX];
__device__ float g_colsum[D];
__device__ float g_colsumsq[D];
__device__ int   g_is32;

__device__ __forceinline__ float lrelu(float s) { return s > 0.f ? s : 0.2f * s; }

// ---------------- zero scratch each call (graph replay safe) ------
__global__ void k_zero(int N) {
    int stride = gridDim.x * blockDim.x;
    int tid = blockIdx.x * blockDim.x + threadIdx.x;
    int total = N * D;
    for (int i = tid; i < total; i += stride) g_agg[i] = 0.f;
    for (int i = tid; i < N; i += stride) g_denom[i] = 0.f;
    if (blockIdx.x == 0 && threadIdx.x < D) {
        g_colsum[threadIdx.x] = 0.f;
        g_colsumsq[threadIdx.x] = 0.f;
    }
}

// ---------------- detect edge_index dtype (int64 vs int32) --------
// If the buffer actually holds int32 pairs, reinterpreting as int64 gives
// values >= 2^32 (or otherwise outside [0,N)) with overwhelming probability.
__global__ void k_detect(const long long* ei, int E, int N) {
    int bad = 0;
    int lim = E < 2048 ? E : 2048;
    for (int i = threadIdx.x; i < lim; i += blockDim.x) {
        long long v = ei[i];
        if (v < 0 || v >= (long long)N) bad = 1;
    }
    int any = __syncthreads_or(bad);
    if (threadIdx.x == 0) g_is32 = any ? 1 : 0;
}

// ---------------- fp32 tiled GEMM:  C = A(MxK) * W(KxD) + bias ----
// BM=64, BN=64, BK=16, 256 threads, 4x4 micro-tile.
__global__ void k_gemm(const float* __restrict__ A, const float* __restrict__ W,
                       const float* __restrict__ bias, int which, int M) {
    __shared__ float As[64][17];
    __shared__ float Bs[16][64];
    float* C = which ? g_xr : g_xl;

    int tx = threadIdx.x % 16;
    int ty = threadIdx.x / 16;
    int row0 = blockIdx.y * 64;
    int col0 = blockIdx.x * 64;

    float acc[4][4] = {};

    for (int k0 = 0; k0 < 256; k0 += 16) {
        // load A tile 64x16 (float4 per thread)
        {
            int t = threadIdx.x;
            int r = t >> 2;            // 0..63
            int c = (t & 3) * 4;       // 0,4,8,12
            int gr = row0 + r;
            float4 v = (gr < M) ? *(const float4*)&A[(size_t)gr * 256 + k0 + c]
                                : make_float4(0.f, 0.f, 0.f, 0.f);
            As[r][c + 0] = v.x; As[r][c + 1] = v.y;
            As[r][c + 2] = v.z; As[r][c + 3] = v.w;
        }
        // load B tile 16x64 (float4 per thread)
        {
            int t = threadIdx.x;
            int r = t >> 4;            // 0..15
            int c = (t & 15) * 4;      // 0..60
            *(float4*)&Bs[r][c] = *(const float4*)&W[(size_t)(k0 + r) * 256 + col0 + c];
        }
        __syncthreads();
#pragma unroll
        for (int kk = 0; kk < 16; kk++) {
            float a[4], b[4];
#pragma unroll
            for (int i = 0; i < 4; i++) a[i] = As[ty * 4 + i][kk];
#pragma unroll
            for (int j = 0; j < 4; j++) b[j] = Bs[kk][tx * 4 + j];
#pragma unroll
            for (int i = 0; i < 4; i++)
#pragma unroll
                for (int j = 0; j < 4; j++) acc[i][j] += a[i] * b[j];
        }
        __syncthreads();
    }

#pragma unroll
    for (int i = 0; i < 4; i++) {
        int gr = row0 + ty * 4 + i;
        if (gr < M) {
#pragma unroll
            for (int j = 0; j < 4; j++) {
                int gc = col0 + tx * 4 + j;
                C[(size_t)gr * 256 + gc] = acc[i][j] + bias[gc];
            }
        }
    }
}

// ---------------- fused edge pass -------------------------------
// One warp per edge (incl. implicit self-loops e in [E, E+N)):
//   e_val = exp( att . leaky_relu(xl[src] + xr[dst]) )
//   denom[dst] += e_val          (scalar atomic, lane 0)
//   agg[dst]   += e_val * xl[src]  (vector red.global.add.v4.f32)
__global__ void k_edge(const void* __restrict__ ei_raw, const float* __restrict__ att,
                       int E, int N) {
    __shared__ float s_att[D];
    for (int i = threadIdx.x; i < D; i += blockDim.x) s_att[i] = att[i];
    __syncthreads();

    int is32 = g_is32;
    int widx = (int)(((unsigned)blockIdx.x * blockDim.x + threadIdx.x) >> 5);
    int lane = threadIdx.x & 31;
    if (widx >= E + N) return;

    int src, dst;
    if (widx < E) {
        if (is32) {
            const int* p = (const int*)ei_raw;
            src = p[widx]; dst = p[E + widx];
        } else {
            const long long* p = (const long long*)ei_raw;
            src = (int)p[widx]; dst = (int)p[E + widx];
        }
    } else {
        src = dst = widx - E;
    }

    const float4* xls = (const float4*)(g_xl + (size_t)src * D);
    const float4* xrd = (const float4*)(g_xr + (size_t)dst * D);
    float4 a0 = xls[lane],      a1 = xls[lane + 32];
    float4 r0 = xrd[lane],      r1 = xrd[lane + 32];
    float4 t0 = ((const float4*)s_att)[lane];
    float4 t1 = ((const float4*)s_att)[lane + 32];

    float p, s;
    s = a0.x + r0.x; p  = t0.x * lrelu(s);
    s = a0.y + r0.y; p += t0.y * lrelu(s);
    s = a0.z + r0.z; p += t0.z * lrelu(s);
    s = a0.w + r0.w; p += t0.w * lrelu(s);
    s = a1.x + r1.x; p += t1.x * lrelu(s);
    s = a1.y + r1.y; p += t1.y * lrelu(s);
    s = a1.z + r1.z; p += t1.z * lrelu(s);
    s = a1.w + r1.w; p += t1.w * lrelu(s);

#pragma unroll
    for (int o = 16; o; o >>= 1) p += __shfl_xor_sync(0xffffffffu, p, o);

    float ev = __expf(p);
    if (lane == 0) atomicAdd(&g_denom[dst], ev);

    float* outp = g_agg + (size_t)dst * D;
    asm volatile("red.global.add.v4.f32 [%0], {%1,%2,%3,%4};"
                 :: "l"(outp + lane * 4),
                    "f"(a0.x * ev), "f"(a0.y * ev), "f"(a0.z * ev), "f"(a0.w * ev)
                 : "memory");
    asm volatile("red.global.add.v4.f32 [%0], {%1,%2,%3,%4};"
                 :: "l"(outp + 128 + lane * 4),
                    "f"(a1.x * ev), "f"(a1.y * ev), "f"(a1.z * ev), "f"(a1.w * ev)
                 : "memory");
}

// ---------------- post: bias + relu + dropout, BN stats ----------
__global__ void k_bnstats(const float* __restrict__ bias, const float* __restrict__ du,
                          int N) {
    int d = threadIdx.x;   // 256 threads = one per column
    float b = bias[d];
    float sum = 0.f, sq = 0.f;
    for (int r = blockIdx.x; r < N; r += gridDim.x) {
        float inv = 1.f / g_denom[r];
        float v = fmaxf(g_agg[(size_t)r * D + d] * inv + b, 0.f);
        v = (du[(size_t)r * D + d] >= 0.5f) ? v * 2.f : 0.f;
        g_agg[(size_t)r * D + d] = v;
        sum += v;
        sq += v * v;
    }
    atomicAdd(&g_colsum[d], sum);
    atomicAdd(&g_colsumsq[d], sq);
}

// ---------------- final BN normalize -----------------------------
__global__ void k_bnnorm(const float* __restrict__ gamma, const float* __restrict__ beta,
                         float* __restrict__ out, int N) {
    int d = threadIdx.x;
    float invN = 1.f / (float)N;
    float mean = g_colsum[d] * invN;
    float var = g_colsumsq[d] * invN - mean * mean;
    float inv = rsqrtf(var + 1e-5f);
    float ga = gamma[d], be = beta[d];
    for (int r = blockIdx.x; r < N; r += gridDim.x) {
        out[(size_t)r * D + d] = ga * (g_agg[(size_t)r * D + d] - mean) * inv + be;
    }
}

// ---------------- launch ------------------------------------------
extern "C" void kernel_launch(void* const* d_in, const int* in_sizes, int n_in,
                              void* d_out, int out_size) {
    (void)n_in; (void)out_size;
    const float* x     = (const float*)d_in[0];
    const void*  ei    = d_in[1];
    const float* Wl    = (const float*)d_in[2];
    const float* bl    = (const float*)d_in[3];
    const float* Wr    = (const float*)d_in[4];
    const float* br    = (const float*)d_in[5];
    const float* att   = (const float*)d_in[6];
    const float* bias  = (const float*)d_in[7];
    const float* gamma = (const float*)d_in[8];
    const float* beta  = (const float*)d_in[9];
    const float* du    = (const float*)d_in[10];

    int N = in_sizes[0] / D;
    int E = in_sizes[1] / 2;

    k_zero<<<2048, 256>>>(N);
    k_detect<<<1, 256>>>((const long long*)ei, E, N);

    dim3 gg(D / 64, (N + 63) / 64);
    k_gemm<<<gg, 256>>>(x, Wl, bl, 0, N);
    k_gemm<<<gg, 256>>>(x, Wr, br, 1, N);

    int warps = E + N;
    int blocks = (warps + 7) / 8;   // 8 warps (256 threads) per block
    k_edge<<<blocks, 256>>>(ei, att, E, N);

    k_bnstats<<<512, 256>>>(bias, du, N);
    k_bnnorm<<<512, 256>>>(gamma, beta, (float*)d_out, N);
}

// round 3
// speedup vs baseline: 1.4549x; 1.4549x over previous
#include <cuda_runtime.h>
#include <cuda_bf16.h>
#include <cstdint>

#define NMAXP 10240          // padded row capacity (N=10000 -> 79*128=10112)
#define D 256

// ---------------- scratch (no allocation allowed) ----------------
__device__ float g_xl[NMAXP * D];
__device__ float g_xr[NMAXP * D];
__device__ float g_agg[NMAXP * D];
__device__ float g_denom[NMAXP];
__device__ float g_colsum[D];
__device__ float g_colsumsq[D];
__device__ int   g_is32;
// bf16 split operands
__device__ __nv_bfloat16 g_ah[NMAXP * D];
__device__ __nv_bfloat16 g_al[NMAXP * D];
__device__ __nv_bfloat16 g_bh[512 * D];   // B[n][k] = W[k][n], n in [0,512)
__device__ __nv_bfloat16 g_bl[512 * D];

__device__ __forceinline__ float lrelu(float s) { return s > 0.f ? s : 0.2f * s; }

// ================= helpers =========================================
__device__ __forceinline__ uint32_t smem_u32(const void* p) {
    uint32_t a;
    asm("{ .reg .u64 t; cvta.to.shared.u64 t, %1; cvt.u32.u64 %0, t; }" : "=r"(a) : "l"(p));
    return a;
}
__device__ __forceinline__ void ldsm_x4(uint32_t& r0, uint32_t& r1, uint32_t& r2,
                                        uint32_t& r3, uint32_t a) {
    asm volatile("ldmatrix.sync.aligned.m8n8.x4.shared.b16 {%0,%1,%2,%3}, [%4];"
                 : "=r"(r0), "=r"(r1), "=r"(r2), "=r"(r3) : "r"(a));
}
__device__ __forceinline__ void mma_bf16(float* d, const uint32_t* a, const uint32_t* b) {
    asm volatile(
        "mma.sync.aligned.m16n8k16.row.col.f32.bf16.bf16.f32 "
        "{%0,%1,%2,%3},{%4,%5,%6,%7},{%8,%9},{%0,%1,%2,%3};"
        : "+f"(d[0]), "+f"(d[1]), "+f"(d[2]), "+f"(d[3])
        : "r"(a[0]), "r"(a[1]), "r"(a[2]), "r"(a[3]), "r"(b[0]), "r"(b[1]));
}
__device__ __forceinline__ void cpasync16(uint32_t dst, const void* src) {
    asm volatile("{ .reg .u64 g; cvta.to.global.u64 g, %1;"
                 "  cp.async.cg.shared.global [%0], [g], 16; }"
                 :: "r"(dst), "l"(src) : "memory");
}

// ---------------- zero scratch each call --------------------------
__global__ void k_zero(int N) {
    int stride = gridDim.x * blockDim.x;
    int tid = blockIdx.x * blockDim.x + threadIdx.x;
    int total = N * D;
    for (int i = tid; i < total; i += stride) g_agg[i] = 0.f;
    for (int i = tid; i < N; i += stride) g_denom[i] = 0.f;
    if (blockIdx.x == 0 && threadIdx.x < D) {
        g_colsum[threadIdx.x] = 0.f;
        g_colsumsq[threadIdx.x] = 0.f;
    }
}

// ---------------- detect edge_index dtype --------------------------
__global__ void k_detect(const long long* ei, int E, int N) {
    int bad = 0;
    int lim = E < 2048 ? E : 2048;
    for (int i = threadIdx.x; i < lim; i += blockDim.x) {
        long long v = ei[i];
        if (v < 0 || v >= (long long)N) bad = 1;
    }
    int any = __syncthreads_or(bad);
    if (threadIdx.x == 0) g_is32 = any ? 1 : 0;
}

// ---------------- fp32 -> bf16 hi/lo split of x (padded rows = 0) --
__global__ void k_conv_x(const float* __restrict__ x, int N, int NPAD) {
    int gid = blockIdx.x * blockDim.x + threadIdx.x;   // one per 4 elements
    int total = NPAD * (D / 4);
    if (gid >= total) return;
    int base = gid * 4;
    int r = base >> 8;
    float4 v = (r < N) ? *(const float4*)(x + base) : make_float4(0.f, 0.f, 0.f, 0.f);
    __nv_bfloat16 h0 = __float2bfloat16(v.x), h1 = __float2bfloat16(v.y);
    __nv_bfloat16 h2 = __float2bfloat16(v.z), h3 = __float2bfloat16(v.w);
    __nv_bfloat16 l0 = __float2bfloat16(v.x - __bfloat162float(h0));
    __nv_bfloat16 l1 = __float2bfloat16(v.y - __bfloat162float(h1));
    __nv_bfloat16 l2 = __float2bfloat16(v.z - __bfloat162float(h2));
    __nv_bfloat16 l3 = __float2bfloat16(v.w - __bfloat162float(h3));
    __nv_bfloat162* ph = (__nv_bfloat162*)(g_ah + base);
    __nv_bfloat162* pl = (__nv_bfloat162*)(g_al + base);
    ph[0] = __nv_bfloat162(h0, h1); ph[1] = __nv_bfloat162(h2, h3);
    pl[0] = __nv_bfloat162(l0, l1); pl[1] = __nv_bfloat162(l2, l3);
}

// ---------------- W -> transposed bf16 hi/lo: B[n][k] = W[k][n] ----
__global__ void k_conv_w(const float* __restrict__ Wl, const float* __restrict__ Wr) {
    int gid = blockIdx.x * blockDim.x + threadIdx.x;   // over 512*256
    if (gid >= 512 * D) return;
    int k = gid >> 9;
    int n = gid & 511;
    float v = (n < 256) ? Wl[(size_t)k * 256 + n] : Wr[(size_t)k * 256 + (n - 256)];
    __nv_bfloat16 h = __float2bfloat16(v);
    __nv_bfloat16 l = __float2bfloat16(v - __bfloat162float(h));
    g_bh[(size_t)n * D + k] = h;
    g_bl[(size_t)n * D + k] = l;
}

// ---------------- HMMA 3xBF16 fused GEMM ----------------------------
// C[NPAD x 512] = A[NPAD x 256] * B^T (B stored [n][k]).
// CTA tile 128x128, 8 warps = 4(M) x 2(N), warp tile 32x64.
// K staged in 4 chunks of 64, cp.async double-buffered.
#define SMSTRIDE 144                      // bytes per smem row (64 bf16 + 8 pad)
#define SMARR    (128 * SMSTRIDE)         // 18432 B per operand array
#define SMSTAGE  (4 * SMARR)              // Ah|Al|Bh|Bl = 73728 B

__global__ void __launch_bounds__(256, 1)
k_hmma(const float* __restrict__ bl, const float* __restrict__ br, int N) {
    extern __shared__ char sm[];
    uint32_t sb = smem_u32(sm);
    const int tid = threadIdx.x, lane = tid & 31, warp = tid >> 5;
    const int wm = warp >> 1, wn = warp & 1;
    const int row0 = blockIdx.y * 128;
    const int ncol0 = blockIdx.x * 128;   // column group within 512

    float acc[2][8][4];
#pragma unroll
    for (int mt = 0; mt < 2; mt++)
#pragma unroll
        for (int nt = 0; nt < 8; nt++)
#pragma unroll
            for (int i = 0; i < 4; i++) acc[mt][nt][i] = 0.f;

    auto issue = [&](int c) {
        uint32_t s0 = sb + (c & 1) * SMSTAGE;
        int kc = c * 64;
#pragma unroll
        for (int i = 0; i < 4; i++) {
            int idx = tid + i * 256;
            int r = idx >> 3, g = idx & 7;
            uint32_t doff = (uint32_t)(r * SMSTRIDE + g * 16);
            size_t aoff = (size_t)(row0 + r) * D + kc + g * 8;
            size_t boff = (size_t)(ncol0 + r) * D + kc + g * 8;
            cpasync16(s0 + doff,              g_ah + aoff);
            cpasync16(s0 + SMARR + doff,      g_al + aoff);
            cpasync16(s0 + 2 * SMARR + doff,  g_bh + boff);
            cpasync16(s0 + 3 * SMARR + doff,  g_bl + boff);
        }
        asm volatile("cp.async.commit_group;" ::: "memory");
    };

    issue(0);
    for (int c = 0; c < 4; c++) {
        if (c < 3) {
            issue(c + 1);
            asm volatile("cp.async.wait_group 1;" ::: "memory");
        } else {
            asm volatile("cp.async.wait_group 0;" ::: "memory");
        }
        __syncthreads();

        uint32_t s0 = sb + (c & 1) * SMSTAGE;
        // A fragment base: lanes 0-15 -> rows, lanes 16-31 -> +16B (k 8-15)
        uint32_t aoffB = (uint32_t)((wm * 32 + (lane & 15)) * SMSTRIDE + (lane >> 4) * 16);
        // B lane mapping for x4 over a pair of n-tiles
        uint32_t nsel = (uint32_t)(lane >> 4);        // second tile of pair
        uint32_t nloc = (uint32_t)(lane & 7);
        uint32_t khalf = (uint32_t)((lane >> 3) & 1);

#pragma unroll
        for (int kt = 0; kt < 4; kt++) {
            uint32_t kb = kt * 32;
            uint32_t ah[2][4], al[2][4];
#pragma unroll
            for (int mt = 0; mt < 2; mt++) {
                uint32_t adr = s0 + aoffB + mt * 16 * SMSTRIDE + kb;
                ldsm_x4(ah[mt][0], ah[mt][1], ah[mt][2], ah[mt][3], adr);
                ldsm_x4(al[mt][0], al[mt][1], al[mt][2], al[mt][3], adr + SMARR);
            }
            uint32_t bh[4][4], blo[4][4];
#pragma unroll
            for (int p = 0; p < 4; p++) {
                uint32_t n = (uint32_t)(wn * 64) + (2 * p + nsel) * 8 + nloc;
                uint32_t adr = s0 + 2 * SMARR + n * SMSTRIDE + kb + khalf * 16;
                ldsm_x4(bh[p][0], bh[p][1], bh[p][2], bh[p][3], adr);
                ldsm_x4(blo[p][0], blo[p][1], blo[p][2], blo[p][3], adr + SMARR);
            }
#pragma unroll
            for (int mt = 0; mt < 2; mt++)
#pragma unroll
                for (int nt = 0; nt < 8; nt++) {
                    const uint32_t* bhp = &bh[nt >> 1][(nt & 1) * 2];
                    const uint32_t* blp = &blo[nt >> 1][(nt & 1) * 2];
                    mma_bf16(acc[mt][nt], ah[mt], bhp);   // hi*hi
                    mma_bf16(acc[mt][nt], al[mt], bhp);   // lo*hi
                    mma_bf16(acc[mt][nt], ah[mt], blp);   // hi*lo
                }
        }
        __syncthreads();
    }

    // epilogue: add bias, write to g_xl / g_xr
    const float* bsel = (blockIdx.x < 2) ? bl : br;
    float* Cout = (blockIdx.x < 2) ? g_xl : g_xr;
    int colbase = (blockIdx.x & 1) * 128 + wn * 64;
#pragma unroll
    for (int mt = 0; mt < 2; mt++) {
        int r0 = row0 + wm * 32 + mt * 16 + (lane >> 2);
#pragma unroll
        for (int nt = 0; nt < 8; nt++) {
            int cc = colbase + nt * 8 + (lane & 3) * 2;
            float b0 = bsel[cc], b1 = bsel[cc + 1];
            if (r0 < N) {
                float2 v = make_float2(acc[mt][nt][0] + b0, acc[mt][nt][1] + b1);
                *(float2*)&Cout[(size_t)r0 * D + cc] = v;
            }
            if (r0 + 8 < N) {
                float2 v = make_float2(acc[mt][nt][2] + b0, acc[mt][nt][3] + b1);
                *(float2*)&Cout[(size_t)(r0 + 8) * D + cc] = v;
            }
        }
    }
}

// ---------------- fused edge pass ----------------------------------
__global__ void k_edge(const void* __restrict__ ei_raw, const float* __restrict__ att,
                       int E, int N) {
    __shared__ float s_att[D];
    for (int i = threadIdx.x; i < D; i += blockDim.x) s_att[i] = att[i];
    __syncthreads();

    int is32 = g_is32;
    int widx = (int)(((unsigned)blockIdx.x * blockDim.x + threadIdx.x) >> 5);
    int lane = threadIdx.x & 31;
    if (widx >= E + N) return;

    int src, dst;
    if (widx < E) {
        if (is32) {
            const int* p = (const int*)ei_raw;
            src = p[widx]; dst = p[E + widx];
        } else {
            const long long* p = (const long long*)ei_raw;
            src = (int)p[widx]; dst = (int)p[E + widx];
        }
    } else {
        src = dst = widx - E;
    }

    const float4* xls = (const float4*)(g_xl + (size_t)src * D);
    const float4* xrd = (const float4*)(g_xr + (size_t)dst * D);
    float4 a0 = xls[lane], a1 = xls[lane + 32];
    float4 r0 = xrd[lane], r1 = xrd[lane + 32];
    float4 t0 = ((const float4*)s_att)[lane];
    float4 t1 = ((const float4*)s_att)[lane + 32];

    float p, s;
    s = a0.x + r0.x; p  = t0.x * lrelu(s);
    s = a0.y + r0.y; p += t0.y * lrelu(s);
    s = a0.z + r0.z; p += t0.z * lrelu(s);
    s = a0.w + r0.w; p += t0.w * lrelu(s);
    s = a1.x + r1.x; p += t1.x * lrelu(s);
    s = a1.y + r1.y; p += t1.y * lrelu(s);
    s = a1.z + r1.z; p += t1.z * lrelu(s);
    s = a1.w + r1.w; p += t1.w * lrelu(s);

#pragma unroll
    for (int o = 16; o; o >>= 1) p += __shfl_xor_sync(0xffffffffu, p, o);

    float ev = __expf(p);
    if (lane == 0) atomicAdd(&g_denom[dst], ev);

    float* outp = g_agg + (size_t)dst * D;
    asm volatile("red.global.add.v4.f32 [%0], {%1,%2,%3,%4};"
                 :: "l"(outp + lane * 4),
                    "f"(a0.x * ev), "f"(a0.y * ev), "f"(a0.z * ev), "f"(a0.w * ev)
                 : "memory");
    asm volatile("red.global.add.v4.f32 [%0], {%1,%2,%3,%4};"
                 :: "l"(outp + 128 + lane * 4),
                    "f"(a1.x * ev), "f"(a1.y * ev), "f"(a1.z * ev), "f"(a1.w * ev)
                 : "memory");
}

// ---------------- post: bias + relu + dropout, BN stats -------------
__global__ void k_bnstats(const float* __restrict__ bias, const float* __restrict__ du,
                          int N) {
    int d = threadIdx.x;
    float b = bias[d];
    float sum = 0.f, sq = 0.f;
    for (int r = blockIdx.x; r < N; r += gridDim.x) {
        float inv = 1.f / g_denom[r];
        float v = fmaxf(g_agg[(size_t)r * D + d] * inv + b, 0.f);
        v = (du[(size_t)r * D + d] >= 0.5f) ? v * 2.f : 0.f;
        g_agg[(size_t)r * D + d] = v;
        sum += v;
        sq += v * v;
    }
    atomicAdd(&g_colsum[d], sum);
    atomicAdd(&g_colsumsq[d], sq);
}

// ---------------- final BN normalize --------------------------------
__global__ void k_bnnorm(const float* __restrict__ gamma, const float* __restrict__ beta,
                         float* __restrict__ out, int N) {
    int d = threadIdx.x;
    float invN = 1.f / (float)N;
    float mean = g_colsum[d] * invN;
    float var = g_colsumsq[d] * invN - mean * mean;
    float inv = rsqrtf(var + 1e-5f);
    float ga = gamma[d], be = beta[d];
    for (int r = blockIdx.x; r < N; r += gridDim.x) {
        out[(size_t)r * D + d] = ga * (g_agg[(size_t)r * D + d] - mean) * inv + be;
    }
}

// ---------------- launch ---------------------------------------------
extern "C" void kernel_launch(void* const* d_in, const int* in_sizes, int n_in,
                              void* d_out, int out_size) {
    (void)n_in; (void)out_size;
    const float* x     = (const float*)d_in[0];
    const void*  ei    = d_in[1];
    const float* Wl    = (const float*)d_in[2];
    const float* bl    = (const float*)d_in[3];
    const float* Wr    = (const float*)d_in[4];
    const float* br    = (const float*)d_in[5];
    const float* att   = (const float*)d_in[6];
    const float* bias  = (const float*)d_in[7];
    const float* gamma = (const float*)d_in[8];
    const float* beta  = (const float*)d_in[9];
    const float* du    = (const float*)d_in[10];

    int N = in_sizes[0] / D;
    int E = in_sizes[1] / 2;
    int mrows = (N + 127) / 128;
    int NPAD = mrows * 128;

    const int SMEM_MMA = 2 * SMSTAGE;   // 147456 bytes
    static int smem_set = 0;
    if (!smem_set) {
        cudaFuncSetAttribute(k_hmma, cudaFuncAttributeMaxDynamicSharedMemorySize, SMEM_MMA);
        smem_set = 1;
    }

    k_zero<<<2048, 256>>>(N);
    k_detect<<<1, 256>>>((const long long*)ei, E, N);

    int convx_threads = NPAD * (D / 4);
    k_conv_x<<<(convx_threads + 255) / 256, 256>>>(x, N, NPAD);
    k_conv_w<<<(512 * D + 255) / 256, 256>>>(Wl, Wr);

    dim3 gg(4, mrows);
    k_hmma<<<gg, 256, SMEM_MMA>>>(bl, br, N);

    int warps = E + N;
    int blocks = (warps + 7) / 8;
    k_edge<<<blocks, 256>>>(ei, att, E, N);

    k_bnstats<<<512, 256>>>(bias, du, N);
    k_bnnorm<<<512, 256>>>(gamma, beta, (float*)d_out, N);
}

// round 4
// speedup vs baseline: 1.4553x; 1.0003x over previous
#include <cuda_runtime.h>
#include <cuda_bf16.h>
#include <cstdint>

#define NMAXP 10240          // padded row capacity (N=10000 -> 79*128=10112)
#define D 256
#define EMAX 200000

// ---------------- scratch (no allocation allowed) ----------------
__device__ float g_xl[NMAXP * D];
__device__ float g_xr[NMAXP * D];
__device__ float g_agg[NMAXP * D];
__device__ float g_colsum[D];
__device__ float g_colsumsq[D];
__device__ int   g_is32;
// CSR by destination
__device__ int g_deg[NMAXP];
__device__ int g_off[NMAXP + 1];
__device__ int g_cur[NMAXP];
__device__ int g_csr_src[EMAX];
// bf16 split operands
__device__ __nv_bfloat16 g_ah[NMAXP * D];
__device__ __nv_bfloat16 g_al[NMAXP * D];
__device__ __nv_bfloat16 g_bh[512 * D];   // B[n][k] = W[k][n], n in [0,512)
__device__ __nv_bfloat16 g_bl[512 * D];

__device__ __forceinline__ float lrelu(float s) { return s > 0.f ? s : 0.2f * s; }

// ================= helpers =========================================
__device__ __forceinline__ uint32_t smem_u32(const void* p) {
    uint32_t a;
    asm("{ .reg .u64 t; cvta.to.shared.u64 t, %1; cvt.u32.u64 %0, t; }" : "=r"(a) : "l"(p));
    return a;
}
__device__ __forceinline__ void ldsm_x4(uint32_t& r0, uint32_t& r1, uint32_t& r2,
                                        uint32_t& r3, uint32_t a) {
    asm volatile("ldmatrix.sync.aligned.m8n8.x4.shared.b16 {%0,%1,%2,%3}, [%4];"
                 : "=r"(r0), "=r"(r1), "=r"(r2), "=r"(r3) : "r"(a));
}
__device__ __forceinline__ void mma_bf16(float* d, const uint32_t* a, const uint32_t* b) {
    asm volatile(
        "mma.sync.aligned.m16n8k16.row.col.f32.bf16.bf16.f32 "
        "{%0,%1,%2,%3},{%4,%5,%6,%7},{%8,%9},{%0,%1,%2,%3};"
        : "+f"(d[0]), "+f"(d[1]), "+f"(d[2]), "+f"(d[3])
        : "r"(a[0]), "r"(a[1]), "r"(a[2]), "r"(a[3]), "r"(b[0]), "r"(b[1]));
}
__device__ __forceinline__ void cpasync16(uint32_t dst, const void* src) {
    asm volatile("{ .reg .u64 g; cvta.to.global.u64 g, %1;"
                 "  cp.async.cg.shared.global [%0], [g], 16; }"
                 :: "r"(dst), "l"(src) : "memory");
}

// ---------------- zero small scratch each call ---------------------
__global__ void k_zero(int N) {
    int tid = blockIdx.x * blockDim.x + threadIdx.x;
    int stride = gridDim.x * blockDim.x;
    for (int i = tid; i < N; i += stride) g_deg[i] = 0;
    if (blockIdx.x == 0 && threadIdx.x < D) {
        g_colsum[threadIdx.x] = 0.f;
        g_colsumsq[threadIdx.x] = 0.f;
    }
}

// ---------------- detect edge_index dtype --------------------------
__global__ void k_detect(const long long* ei, int E, int N) {
    int bad = 0;
    int lim = E < 2048 ? E : 2048;
    for (int i = threadIdx.x; i < lim; i += blockDim.x) {
        long long v = ei[i];
        if (v < 0 || v >= (long long)N) bad = 1;
    }
    int any = __syncthreads_or(bad);
    if (threadIdx.x == 0) g_is32 = any ? 1 : 0;
}

// ---------------- CSR build: count ---------------------------------
__global__ void k_count(const void* __restrict__ ei, int E) {
    int i = blockIdx.x * blockDim.x + threadIdx.x;
    if (i >= E) return;
    int dst = g_is32 ? ((const int*)ei)[E + i] : (int)((const long long*)ei)[E + i];
    atomicAdd(&g_deg[dst], 1);
}

// ---------------- CSR build: single-block exclusive scan ------------
__global__ void k_scan(int N) {
    __shared__ int part[1024];
    int t = threadIdx.x;
    int chunk = (N + 1023) >> 10;
    int beg = t * chunk;
    int end = min(beg + chunk, N);
    int s = 0;
    for (int i = beg; i < end; i++) s += g_deg[i];
    part[t] = s;
    __syncthreads();
    for (int off = 1; off < 1024; off <<= 1) {
        int v = (t >= off) ? part[t - off] : 0;
        __syncthreads();
        part[t] += v;
        __syncthreads();
    }
    int run = (t > 0) ? part[t - 1] : 0;
    for (int i = beg; i < end; i++) {
        g_off[i] = run;
        g_cur[i] = run;
        run += g_deg[i];
    }
    if (t == 0) g_off[N] = part[1023];
}

// ---------------- CSR build: fill -----------------------------------
__global__ void k_fill(const void* __restrict__ ei, int E) {
    int i = blockIdx.x * blockDim.x + threadIdx.x;
    if (i >= E) return;
    int src, dst;
    if (g_is32) {
        const int* p = (const int*)ei;
        src = p[i]; dst = p[E + i];
    } else {
        const long long* p = (const long long*)ei;
        src = (int)p[i]; dst = (int)p[E + i];
    }
    int pos = atomicAdd(&g_cur[dst], 1);
    g_csr_src[pos] = src;
}

// ---------------- fp32 -> bf16 hi/lo split of x (padded rows = 0) --
__global__ void k_conv_x(const float* __restrict__ x, int N, int NPAD) {
    int gid = blockIdx.x * blockDim.x + threadIdx.x;   // one per 4 elements
    int total = NPAD * (D / 4);
    if (gid >= total) return;
    int base = gid * 4;
    int r = base >> 8;
    float4 v = (r < N) ? *(const float4*)(x + base) : make_float4(0.f, 0.f, 0.f, 0.f);
    __nv_bfloat16 h0 = __float2bfloat16(v.x), h1 = __float2bfloat16(v.y);
    __nv_bfloat16 h2 = __float2bfloat16(v.z), h3 = __float2bfloat16(v.w);
    __nv_bfloat16 l0 = __float2bfloat16(v.x - __bfloat162float(h0));
    __nv_bfloat16 l1 = __float2bfloat16(v.y - __bfloat162float(h1));
    __nv_bfloat16 l2 = __float2bfloat16(v.z - __bfloat162float(h2));
    __nv_bfloat16 l3 = __float2bfloat16(v.w - __bfloat162float(h3));
    __nv_bfloat162* ph = (__nv_bfloat162*)(g_ah + base);
    __nv_bfloat162* pl = (__nv_bfloat162*)(g_al + base);
    ph[0] = __nv_bfloat162(h0, h1); ph[1] = __nv_bfloat162(h2, h3);
    pl[0] = __nv_bfloat162(l0, l1); pl[1] = __nv_bfloat162(l2, l3);
}

// ---------------- W transpose via smem tiles: B[n][k] = W[k][n] -----
// grid (16 n-tiles, 8 k-tiles), 256 threads.
__global__ void k_conv_w(const float* __restrict__ Wl, const float* __restrict__ Wr) {
    __shared__ __nv_bfloat16 sh[32][33];
    __shared__ __nv_bfloat16 sl[32][33];
    int n0 = blockIdx.x * 32;
    int k0 = blockIdx.y * 32;
    int tid = threadIdx.x;
    int c = tid & 31;          // n offset (coalesced read)
    int r = tid >> 5;          // 0..7
#pragma unroll
    for (int i = 0; i < 4; i++) {
        int k = r + i * 8;
        int n = n0 + c;
        float v = (n < 256) ? Wl[(size_t)(k0 + k) * 256 + n]
                            : Wr[(size_t)(k0 + k) * 256 + (n - 256)];
        __nv_bfloat16 h = __float2bfloat16(v);
        sh[k][c] = h;
        sl[k][c] = __float2bfloat16(v - __bfloat162float(h));
    }
    __syncthreads();
    int nn = tid >> 4;         // 0..15
    int kk = (tid & 15) * 2;   // even k
#pragma unroll
    for (int i = 0; i < 2; i++) {
        int nl = nn + i * 16;
        int n = n0 + nl;
        *(__nv_bfloat162*)&g_bh[(size_t)n * D + k0 + kk] = __nv_bfloat162(sh[kk][nl], sh[kk + 1][nl]);
        *(__nv_bfloat162*)&g_bl[(size_t)n * D + k0 + kk] = __nv_bfloat162(sl[kk][nl], sl[kk + 1][nl]);
    }
}

// ---------------- HMMA 3xBF16 fused GEMM ----------------------------
#define SMSTRIDE 144
#define SMARR    (128 * SMSTRIDE)
#define SMSTAGE  (4 * SMARR)

__global__ void __launch_bounds__(256, 1)
k_hmma(const float* __restrict__ bl, const float* __restrict__ br, int N) {
    extern __shared__ char sm[];
    uint32_t sb = smem_u32(sm);
    const int tid = threadIdx.x, lane = tid & 31, warp = tid >> 5;
    const int wm = warp >> 1, wn = warp & 1;
    const int row0 = blockIdx.y * 128;
    const int ncol0 = blockIdx.x * 128;

    float acc[2][8][4];
#pragma unroll
    for (int mt = 0; mt < 2; mt++)
#pragma unroll
        for (int nt = 0; nt < 8; nt++)
#pragma unroll
            for (int i = 0; i < 4; i++) acc[mt][nt][i] = 0.f;

    auto issue = [&](int c) {
        uint32_t s0 = sb + (c & 1) * SMSTAGE;
        int kc = c * 64;
#pragma unroll
        for (int i = 0; i < 4; i++) {
            int idx = tid + i * 256;
            int r = idx >> 3, g = idx & 7;
            uint32_t doff = (uint32_t)(r * SMSTRIDE + g * 16);
            size_t aoff = (size_t)(row0 + r) * D + kc + g * 8;
            size_t boff = (size_t)(ncol0 + r) * D + kc + g * 8;
            cpasync16(s0 + doff,              g_ah + aoff);
            cpasync16(s0 + SMARR + doff,      g_al + aoff);
            cpasync16(s0 + 2 * SMARR + doff,  g_bh + boff);
            cpasync16(s0 + 3 * SMARR + doff,  g_bl + boff);
        }
        asm volatile("cp.async.commit_group;" ::: "memory");
    };

    issue(0);
    for (int c = 0; c < 4; c++) {
        if (c < 3) {
            issue(c + 1);
            asm volatile("cp.async.wait_group 1;" ::: "memory");
        } else {
            asm volatile("cp.async.wait_group 0;" ::: "memory");
        }
        __syncthreads();

        uint32_t s0 = sb + (c & 1) * SMSTAGE;
        uint32_t aoffB = (uint32_t)((wm * 32 + (lane & 15)) * SMSTRIDE + (lane >> 4) * 16);
        uint32_t nsel = (uint32_t)(lane >> 4);
        uint32_t nloc = (uint32_t)(lane & 7);
        uint32_t khalf = (uint32_t)((lane >> 3) & 1);

#pragma unroll
        for (int kt = 0; kt < 4; kt++) {
            uint32_t kb = kt * 32;
            uint32_t ah[2][4], al[2][4];
#pragma unroll
            for (int mt = 0; mt < 2; mt++) {
                uint32_t adr = s0 + aoffB + mt * 16 * SMSTRIDE + kb;
                ldsm_x4(ah[mt][0], ah[mt][1], ah[mt][2], ah[mt][3], adr);
                ldsm_x4(al[mt][0], al[mt][1], al[mt][2], al[mt][3], adr + SMARR);
            }
            uint32_t bh[4][4], blo[4][4];
#pragma unroll
            for (int p = 0; p < 4; p++) {
                uint32_t n = (uint32_t)(wn * 64) + (2 * p + nsel) * 8 + nloc;
                uint32_t adr = s0 + 2 * SMARR + n * SMSTRIDE + kb + khalf * 16;
                ldsm_x4(bh[p][0], bh[p][1], bh[p][2], bh[p][3], adr);
                ldsm_x4(blo[p][0], blo[p][1], blo[p][2], blo[p][3], adr + SMARR);
            }
#pragma unroll
            for (int mt = 0; mt < 2; mt++)
#pragma unroll
                for (int nt = 0; nt < 8; nt++) {
                    const uint32_t* bhp = &bh[nt >> 1][(nt & 1) * 2];
                    const uint32_t* blp = &blo[nt >> 1][(nt & 1) * 2];
                    mma_bf16(acc[mt][nt], ah[mt], bhp);
                    mma_bf16(acc[mt][nt], al[mt], bhp);
                    mma_bf16(acc[mt][nt], ah[mt], blp);
                }
        }
        __syncthreads();
    }

    const float* bsel = (blockIdx.x < 2) ? bl : br;
    float* Cout = (blockIdx.x < 2) ? g_xl : g_xr;
    int colbase = (blockIdx.x & 1) * 128 + wn * 64;
#pragma unroll
    for (int mt = 0; mt < 2; mt++) {
        int r0 = row0 + wm * 32 + mt * 16 + (lane >> 2);
#pragma unroll
        for (int nt = 0; nt < 8; nt++) {
            int cc = colbase + nt * 8 + (lane & 3) * 2;
            float b0 = bsel[cc], b1 = bsel[cc + 1];
            if (r0 < N) {
                float2 v = make_float2(acc[mt][nt][0] + b0, acc[mt][nt][1] + b1);
                *(float2*)&Cout[(size_t)r0 * D + cc] = v;
            }
            if (r0 + 8 < N) {
                float2 v = make_float2(acc[mt][nt][2] + b0, acc[mt][nt][3] + b1);
                *(float2*)&Cout[(size_t)(r0 + 8) * D + cc] = v;
            }
        }
    }
}

// ---------------- dst-centric aggregation + epilogue -----------------
// One warp per destination node; 8 warps per block.
// acc = sum_e exp(att.lrelu(xl[src]+xr[dst])) * xl[src]  (incl. self-loop)
// out = relu(acc/den + bias) * dropout; col sums accumulated for BN.
__global__ void __launch_bounds__(256)
k_agg(const float* __restrict__ att, const float* __restrict__ bias,
      const float* __restrict__ du, int N) {
    __shared__ float s_sum[D];
    __shared__ float s_sq[D];
    int tid = threadIdx.x, warp = tid >> 5, lane = tid & 31;
    for (int i = tid; i < D; i += 256) { s_sum[i] = 0.f; s_sq[i] = 0.f; }
    __syncthreads();

    int dst = blockIdx.x * 8 + warp;
    if (dst < N) {
        const float4* xrd = (const float4*)(g_xr + (size_t)dst * D);
        float4 r0 = xrd[lane], r1 = xrd[lane + 32];
        float4 t0 = ((const float4*)att)[lane];
        float4 t1 = ((const float4*)att)[lane + 32];

        float4 acc0 = make_float4(0.f, 0.f, 0.f, 0.f);
        float4 acc1 = make_float4(0.f, 0.f, 0.f, 0.f);
        float den = 0.f;

        int off = g_off[dst];
        int end = g_off[dst + 1];

        // process self-loop (src = dst) + CSR edges
        for (int base = off - 1; base < end; base += 32) {
            int nsrc = -1;
            int idx = base + lane;
            if (idx >= off && idx < end) nsrc = g_csr_src[idx];
            else if (idx == off - 1) nsrc = dst;     // self-loop slot
            int m = min(32, end - base);
            for (int e = 0; e < m; e++) {
                int src = __shfl_sync(0xffffffffu, nsrc, e);
                const float4* xls = (const float4*)(g_xl + (size_t)src * D);
                float4 a0 = xls[lane], a1 = xls[lane + 32];
                float s, p;
                s = a0.x + r0.x; p  = t0.x * lrelu(s);
                s = a0.y + r0.y; p += t0.y * lrelu(s);
                s = a0.z + r0.z; p += t0.z * lrelu(s);
                s = a0.w + r0.w; p += t0.w * lrelu(s);
                s = a1.x + r1.x; p += t1.x * lrelu(s);
                s = a1.y + r1.y; p += t1.y * lrelu(s);
                s = a1.z + r1.z; p += t1.z * lrelu(s);
                s = a1.w + r1.w; p += t1.w * lrelu(s);
#pragma unroll
                for (int o = 16; o; o >>= 1) p += __shfl_xor_sync(0xffffffffu, p, o);
                float ev = __expf(p);
                den += ev;
                acc0.x += ev * a0.x; acc0.y += ev * a0.y;
                acc0.z += ev * a0.z; acc0.w += ev * a0.w;
                acc1.x += ev * a1.x; acc1.y += ev * a1.y;
                acc1.z += ev * a1.z; acc1.w += ev * a1.w;
            }
        }

        float inv = 1.f / den;
        const float4* dup = (const float4*)(du + (size_t)dst * D);
        float4 u0 = dup[lane], u1 = dup[lane + 32];
        const float4* bp = (const float4*)bias;
        float4 b0 = bp[lane], b1 = bp[lane + 32];

        float4 v0, v1;
        v0.x = fmaxf(acc0.x * inv + b0.x, 0.f); v0.x = (u0.x >= 0.5f) ? v0.x * 2.f : 0.f;
        v0.y = fmaxf(acc0.y * inv + b0.y, 0.f); v0.y = (u0.y >= 0.5f) ? v0.y * 2.f : 0.f;
        v0.z = fmaxf(acc0.z * inv + b0.z, 0.f); v0.z = (u0.z >= 0.5f) ? v0.z * 2.f : 0.f;
        v0.w = fmaxf(acc0.w * inv + b0.w, 0.f); v0.w = (u0.w >= 0.5f) ? v0.w * 2.f : 0.f;
        v1.x = fmaxf(acc1.x * inv + b1.x, 0.f); v1.x = (u1.x >= 0.5f) ? v1.x * 2.f : 0.f;
        v1.y = fmaxf(acc1.y * inv + b1.y, 0.f); v1.y = (u1.y >= 0.5f) ? v1.y * 2.f : 0.f;
        v1.z = fmaxf(acc1.z * inv + b1.z, 0.f); v1.z = (u1.z >= 0.5f) ? v1.z * 2.f : 0.f;
        v1.w = fmaxf(acc1.w * inv + b1.w, 0.f); v1.w = (u1.w >= 0.5f) ? v1.w * 2.f : 0.f;

        float4* op = (float4*)(g_agg + (size_t)dst * D);
        op[lane] = v0; op[lane + 32] = v1;

        int c0 = lane * 4, c1 = 128 + lane * 4;
        atomicAdd(&s_sum[c0 + 0], v0.x); atomicAdd(&s_sq[c0 + 0], v0.x * v0.x);
        atomicAdd(&s_sum[c0 + 1], v0.y); atomicAdd(&s_sq[c0 + 1], v0.y * v0.y);
        atomicAdd(&s_sum[c0 + 2], v0.z); atomicAdd(&s_sq[c0 + 2], v0.z * v0.z);
        atomicAdd(&s_sum[c0 + 3], v0.w); atomicAdd(&s_sq[c0 + 3], v0.w * v0.w);
        atomicAdd(&s_sum[c1 + 0], v1.x); atomicAdd(&s_sq[c1 + 0], v1.x * v1.x);
        atomicAdd(&s_sum[c1 + 1], v1.y); atomicAdd(&s_sq[c1 + 1], v1.y * v1.y);
        atomicAdd(&s_sum[c1 + 2], v1.z); atomicAdd(&s_sq[c1 + 2], v1.z * v1.z);
        atomicAdd(&s_sum[c1 + 3], v1.w); atomicAdd(&s_sq[c1 + 3], v1.w * v1.w);
    }
    __syncthreads();
    atomicAdd(&g_colsum[tid], s_sum[tid]);
    atomicAdd(&g_colsumsq[tid], s_sq[tid]);
}

// ---------------- final BN normalize --------------------------------
__global__ void k_bnnorm(const float* __restrict__ gamma, const float* __restrict__ beta,
                         float* __restrict__ out, int N) {
    int d = threadIdx.x;
    float invN = 1.f / (float)N;
    float mean = g_colsum[d] * invN;
    float var = g_colsumsq[d] * invN - mean * mean;
    float inv = rsqrtf(var + 1e-5f);
    float ga = gamma[d], be = beta[d];
    for (int r = blockIdx.x; r < N; r += gridDim.x) {
        out[(size_t)r * D + d] = ga * (g_agg[(size_t)r * D + d] - mean) * inv + be;
    }
}

// ---------------- launch ---------------------------------------------
extern "C" void kernel_launch(void* const* d_in, const int* in_sizes, int n_in,
                              void* d_out, int out_size) {
    (void)n_in; (void)out_size;
    const float* x     = (const float*)d_in[0];
    const void*  ei    = d_in[1];
    const float* Wl    = (const float*)d_in[2];
    const float* bl    = (const float*)d_in[3];
    const float* Wr    = (const float*)d_in[4];
    const float* br    = (const float*)d_in[5];
    const float* att   = (const float*)d_in[6];
    const float* bias  = (const float*)d_in[7];
    const float* gamma = (const float*)d_in[8];
    const float* beta  = (const float*)d_in[9];
    const float* du    = (const float*)d_in[10];

    int N = in_sizes[0] / D;
    int E = in_sizes[1] / 2;
    int mrows = (N + 127) / 128;
    int NPAD = mrows * 128;

    const int SMEM_MMA = 2 * SMSTAGE;   // 147456 bytes
    static int smem_set = 0;
    if (!smem_set) {
        cudaFuncSetAttribute(k_hmma, cudaFuncAttributeMaxDynamicSharedMemorySize, SMEM_MMA);
        smem_set = 1;
    }

    k_zero<<<40, 256>>>(N);
    k_detect<<<1, 256>>>((const long long*)ei, E, N);

    // CSR build
    k_count<<<(E + 255) / 256, 256>>>(ei, E);
    k_scan<<<1, 1024>>>(N);
    k_fill<<<(E + 255) / 256, 256>>>(ei, E);

    // bf16 split conversions
    int convx_threads = NPAD * (D / 4);
    k_conv_x<<<(convx_threads + 255) / 256, 256>>>(x, N, NPAD);
    dim3 gw(16, 8);
    k_conv_w<<<gw, 256>>>(Wl, Wr);

    // fused dual GEMM
    dim3 gg(4, mrows);
    k_hmma<<<gg, 256, SMEM_MMA>>>(bl, br, N);

    // dst-centric aggregation + epilogue + BN stats
    k_agg<<<(N + 7) / 8, 256>>>(att, bias, du, N);

    // BN normalize
    k_bnnorm<<<512, 256>>>(gamma, beta, (float*)d_out, N);
}

// round 5
// speedup vs baseline: 1.6317x; 1.1212x over previous
#include <cuda_runtime.h>
#include <cuda_bf16.h>
#include <cstdint>

#define NMAXP 10240          // padded row capacity (N=10000 -> 79*128=10112)
#define D 256
#define EMAX 200000

// ---------------- scratch (no allocation allowed) ----------------
__device__ float g_xl[NMAXP * D];
__device__ float g_xr[NMAXP * D];
__device__ float g_agg[NMAXP * D];
__device__ float g_colsum[D];
__device__ float g_colsumsq[D];
__device__ int   g_is32;
__device__ int   g_total;
// CSR by destination (unordered base allocation)
__device__ int g_deg[NMAXP];
__device__ int g_off[NMAXP];
__device__ int g_cur[NMAXP];
__device__ int g_csr_src[EMAX];
// bf16 split operands
__device__ __nv_bfloat16 g_ah[NMAXP * D];
__device__ __nv_bfloat16 g_al[NMAXP * D];
__device__ __nv_bfloat16 g_bh[512 * D];   // B[n][k] = W[k][n], n in [0,512)
__device__ __nv_bfloat16 g_bl[512 * D];

__device__ __forceinline__ float lrelu(float s) { return s > 0.f ? s : 0.2f * s; }

// ================= helpers =========================================
__device__ __forceinline__ uint32_t smem_u32(const void* p) {
    uint32_t a;
    asm("{ .reg .u64 t; cvta.to.shared.u64 t, %1; cvt.u32.u64 %0, t; }" : "=r"(a) : "l"(p));
    return a;
}
__device__ __forceinline__ void ldsm_x4(uint32_t& r0, uint32_t& r1, uint32_t& r2,
                                        uint32_t& r3, uint32_t a) {
    asm volatile("ldmatrix.sync.aligned.m8n8.x4.shared.b16 {%0,%1,%2,%3}, [%4];"
                 : "=r"(r0), "=r"(r1), "=r"(r2), "=r"(r3) : "r"(a));
}
__device__ __forceinline__ void mma_bf16(float* d, const uint32_t* a, const uint32_t* b) {
    asm volatile(
        "mma.sync.aligned.m16n8k16.row.col.f32.bf16.bf16.f32 "
        "{%0,%1,%2,%3},{%4,%5,%6,%7},{%8,%9},{%0,%1,%2,%3};"
        : "+f"(d[0]), "+f"(d[1]), "+f"(d[2]), "+f"(d[3])
        : "r"(a[0]), "r"(a[1]), "r"(a[2]), "r"(a[3]), "r"(b[0]), "r"(b[1]));
}
__device__ __forceinline__ void cpasync16(uint32_t dst, const void* src) {
    asm volatile("{ .reg .u64 g; cvta.to.global.u64 g, %1;"
                 "  cp.async.cg.shared.global [%0], [g], 16; }"
                 :: "r"(dst), "l"(src) : "memory");
}

// ---------------- init: zero counters + detect dtype ----------------
__global__ void k_init(const long long* ei, int E, int N) {
    int tid = blockIdx.x * blockDim.x + threadIdx.x;
    int stride = gridDim.x * blockDim.x;
    for (int i = tid; i < N; i += stride) g_deg[i] = 0;
    if (blockIdx.x == 0) {
        if (threadIdx.x < D) {
            g_colsum[threadIdx.x] = 0.f;
            g_colsumsq[threadIdx.x] = 0.f;
        }
        if (threadIdx.x == 0) g_total = 0;
    }
    if (blockIdx.x == 1) {
        int bad = 0;
        int lim = E < 2048 ? E : 2048;
        for (int i = threadIdx.x; i < lim; i += blockDim.x) {
            long long v = ei[i];
            if (v < 0 || v >= (long long)N) bad = 1;
        }
        int any = __syncthreads_or(bad);
        if (threadIdx.x == 0) g_is32 = any ? 1 : 0;
    }
}

// ---------------- CSR build: count ---------------------------------
__global__ void k_count(const void* __restrict__ ei, int E) {
    int i = blockIdx.x * blockDim.x + threadIdx.x;
    if (i >= E) return;
    int dst = g_is32 ? ((const int*)ei)[E + i] : (int)((const long long*)ei)[E + i];
    atomicAdd(&g_deg[dst], 1);
}

// ---------------- CSR build: unordered base allocation ---------------
// Warp-aggregated atomicAdd on one counter; segment order is irrelevant
// because the aggregation is commutative.
__global__ void k_alloc(int N) {
    int i = blockIdx.x * blockDim.x + threadIdx.x;
    int lane = threadIdx.x & 31;
    int d = (i < N) ? g_deg[i] : 0;
    int p = d;
#pragma unroll
    for (int o = 1; o < 32; o <<= 1) {
        int t = __shfl_up_sync(0xffffffffu, p, o);
        if (lane >= o) p += t;
    }
    int total = __shfl_sync(0xffffffffu, p, 31);
    int base = 0;
    if (lane == 0) base = atomicAdd(&g_total, total);
    base = __shfl_sync(0xffffffffu, base, 0);
    int off = base + p - d;
    if (i < N) {
        g_off[i] = off;
        g_cur[i] = off;
    }
}

// ---------------- CSR build: fill -----------------------------------
__global__ void k_fill(const void* __restrict__ ei, int E) {
    int i = blockIdx.x * blockDim.x + threadIdx.x;
    if (i >= E) return;
    int src, dst;
    if (g_is32) {
        const int* p = (const int*)ei;
        src = p[i]; dst = p[E + i];
    } else {
        const long long* p = (const long long*)ei;
        src = (int)p[i]; dst = (int)p[E + i];
    }
    int pos = atomicAdd(&g_cur[dst], 1);
    g_csr_src[pos] = src;
}

// ---------------- fp32 -> bf16 hi/lo split of x (padded rows = 0) --
__global__ void k_conv_x(const float* __restrict__ x, int N, int NPAD) {
    int gid = blockIdx.x * blockDim.x + threadIdx.x;   // one per 4 elements
    int total = NPAD * (D / 4);
    if (gid >= total) return;
    int base = gid * 4;
    int r = base >> 8;
    float4 v = (r < N) ? *(const float4*)(x + base) : make_float4(0.f, 0.f, 0.f, 0.f);
    __nv_bfloat16 h0 = __float2bfloat16(v.x), h1 = __float2bfloat16(v.y);
    __nv_bfloat16 h2 = __float2bfloat16(v.z), h3 = __float2bfloat16(v.w);
    __nv_bfloat16 l0 = __float2bfloat16(v.x - __bfloat162float(h0));
    __nv_bfloat16 l1 = __float2bfloat16(v.y - __bfloat162float(h1));
    __nv_bfloat16 l2 = __float2bfloat16(v.z - __bfloat162float(h2));
    __nv_bfloat16 l3 = __float2bfloat16(v.w - __bfloat162float(h3));
    __nv_bfloat162* ph = (__nv_bfloat162*)(g_ah + base);
    __nv_bfloat162* pl = (__nv_bfloat162*)(g_al + base);
    ph[0] = __nv_bfloat162(h0, h1); ph[1] = __nv_bfloat162(h2, h3);
    pl[0] = __nv_bfloat162(l0, l1); pl[1] = __nv_bfloat162(l2, l3);
}

// ---------------- W transpose via smem tiles: B[n][k] = W[k][n] -----
__global__ void k_conv_w(const float* __restrict__ Wl, const float* __restrict__ Wr) {
    __shared__ __nv_bfloat16 sh[32][33];
    __shared__ __nv_bfloat16 sl[32][33];
    int n0 = blockIdx.x * 32;
    int k0 = blockIdx.y * 32;
    int tid = threadIdx.x;
    int c = tid & 31;
    int r = tid >> 5;
#pragma unroll
    for (int i = 0; i < 4; i++) {
        int k = r + i * 8;
        int n = n0 + c;
        float v = (n < 256) ? Wl[(size_t)(k0 + k) * 256 + n]
                            : Wr[(size_t)(k0 + k) * 256 + (n - 256)];
        __nv_bfloat16 h = __float2bfloat16(v);
        sh[k][c] = h;
        sl[k][c] = __float2bfloat16(v - __bfloat162float(h));
    }
    __syncthreads();
    int nn = tid >> 4;
    int kk = (tid & 15) * 2;
#pragma unroll
    for (int i = 0; i < 2; i++) {
        int nl = nn + i * 16;
        int n = n0 + nl;
        *(__nv_bfloat162*)&g_bh[(size_t)n * D + k0 + kk] = __nv_bfloat162(sh[kk][nl], sh[kk + 1][nl]);
        *(__nv_bfloat162*)&g_bl[(size_t)n * D + k0 + kk] = __nv_bfloat162(sl[kk][nl], sl[kk + 1][nl]);
    }
}

// ---------------- HMMA 3xBF16 fused GEMM ----------------------------
#define SMSTRIDE 144
#define SMARR    (128 * SMSTRIDE)
#define SMSTAGE  (4 * SMARR)

__global__ void __launch_bounds__(256, 1)
k_hmma(const float* __restrict__ bl, const float* __restrict__ br, int N) {
    extern __shared__ char sm[];
    uint32_t sb = smem_u32(sm);
    const int tid = threadIdx.x, lane = tid & 31, warp = tid >> 5;
    const int wm = warp >> 1, wn = warp & 1;
    const int row0 = blockIdx.y * 128;
    const int ncol0 = blockIdx.x * 128;

    float acc[2][8][4];
#pragma unroll
    for (int mt = 0; mt < 2; mt++)
#pragma unroll
        for (int nt = 0; nt < 8; nt++)
#pragma unroll
            for (int i = 0; i < 4; i++) acc[mt][nt][i] = 0.f;

    auto issue = [&](int c) {
        uint32_t s0 = sb + (c & 1) * SMSTAGE;
        int kc = c * 64;
#pragma unroll
        for (int i = 0; i < 4; i++) {
            int idx = tid + i * 256;
            int r = idx >> 3, g = idx & 7;
            uint32_t doff = (uint32_t)(r * SMSTRIDE + g * 16);
            size_t aoff = (size_t)(row0 + r) * D + kc + g * 8;
            size_t boff = (size_t)(ncol0 + r) * D + kc + g * 8;
            cpasync16(s0 + doff,              g_ah + aoff);
            cpasync16(s0 + SMARR + doff,      g_al + aoff);
            cpasync16(s0 + 2 * SMARR + doff,  g_bh + boff);
            cpasync16(s0 + 3 * SMARR + doff,  g_bl + boff);
        }
        asm volatile("cp.async.commit_group;" ::: "memory");
    };

    issue(0);
    for (int c = 0; c < 4; c++) {
        if (c < 3) {
            issue(c + 1);
            asm volatile("cp.async.wait_group 1;" ::: "memory");
        } else {
            asm volatile("cp.async.wait_group 0;" ::: "memory");
        }
        __syncthreads();

        uint32_t s0 = sb + (c & 1) * SMSTAGE;
        uint32_t aoffB = (uint32_t)((wm * 32 + (lane & 15)) * SMSTRIDE + (lane >> 4) * 16);
        uint32_t nsel = (uint32_t)(lane >> 4);
        uint32_t nloc = (uint32_t)(lane & 7);
        uint32_t khalf = (uint32_t)((lane >> 3) & 1);

#pragma unroll
        for (int kt = 0; kt < 4; kt++) {
            uint32_t kb = kt * 32;
            uint32_t ah[2][4], al[2][4];
#pragma unroll
            for (int mt = 0; mt < 2; mt++) {
                uint32_t adr = s0 + aoffB + mt * 16 * SMSTRIDE + kb;
                ldsm_x4(ah[mt][0], ah[mt][1], ah[mt][2], ah[mt][3], adr);
                ldsm_x4(al[mt][0], al[mt][1], al[mt][2], al[mt][3], adr + SMARR);
            }
            uint32_t bh[4][4], blo[4][4];
#pragma unroll
            for (int p = 0; p < 4; p++) {
                uint32_t n = (uint32_t)(wn * 64) + (2 * p + nsel) * 8 + nloc;
                uint32_t adr = s0 + 2 * SMARR + n * SMSTRIDE + kb + khalf * 16;
                ldsm_x4(bh[p][0], bh[p][1], bh[p][2], bh[p][3], adr);
                ldsm_x4(blo[p][0], blo[p][1], blo[p][2], blo[p][3], adr + SMARR);
            }
#pragma unroll
            for (int mt = 0; mt < 2; mt++)
#pragma unroll
                for (int nt = 0; nt < 8; nt++) {
                    const uint32_t* bhp = &bh[nt >> 1][(nt & 1) * 2];
                    const uint32_t* blp = &blo[nt >> 1][(nt & 1) * 2];
                    mma_bf16(acc[mt][nt], ah[mt], bhp);
                    mma_bf16(acc[mt][nt], al[mt], bhp);
                    mma_bf16(acc[mt][nt], ah[mt], blp);
                }
        }
        __syncthreads();
    }

    const float* bsel = (blockIdx.x < 2) ? bl : br;
    float* Cout = (blockIdx.x < 2) ? g_xl : g_xr;
    int colbase = (blockIdx.x & 1) * 128 + wn * 64;
#pragma unroll
    for (int mt = 0; mt < 2; mt++) {
        int r0 = row0 + wm * 32 + mt * 16 + (lane >> 2);
#pragma unroll
        for (int nt = 0; nt < 8; nt++) {
            int cc = colbase + nt * 8 + (lane & 3) * 2;
            float b0 = bsel[cc], b1 = bsel[cc + 1];
            if (r0 < N) {
                float2 v = make_float2(acc[mt][nt][0] + b0, acc[mt][nt][1] + b1);
                *(float2*)&Cout[(size_t)r0 * D + cc] = v;
            }
            if (r0 + 8 < N) {
                float2 v = make_float2(acc[mt][nt][2] + b0, acc[mt][nt][3] + b1);
                *(float2*)&Cout[(size_t)(r0 + 8) * D + cc] = v;
            }
        }
    }
}

// ---------------- dst-centric aggregation + epilogue -----------------
__global__ void __launch_bounds__(256)
k_agg(const float* __restrict__ att, const float* __restrict__ bias,
      const float* __restrict__ du, int N) {
    __shared__ float s_sum[D];
    __shared__ float s_sq[D];
    int tid = threadIdx.x, warp = tid >> 5, lane = tid & 31;
    for (int i = tid; i < D; i += 256) { s_sum[i] = 0.f; s_sq[i] = 0.f; }
    __syncthreads();

    int dst = blockIdx.x * 8 + warp;
    if (dst < N) {
        const float4* xrd = (const float4*)(g_xr + (size_t)dst * D);
        float4 r0 = xrd[lane], r1 = xrd[lane + 32];
        float4 t0 = ((const float4*)att)[lane];
        float4 t1 = ((const float4*)att)[lane + 32];

        float4 acc0 = make_float4(0.f, 0.f, 0.f, 0.f);
        float4 acc1 = make_float4(0.f, 0.f, 0.f, 0.f);
        float den = 0.f;

        int off = g_off[dst];
        int end = g_cur[dst];           // after k_fill, cur == off + deg

        // process self-loop (src = dst) + CSR edges
        for (int base = off - 1; base < end; base += 32) {
            int nsrc = -1;
            int idx = base + lane;
            if (idx >= off && idx < end) nsrc = g_csr_src[idx];
            else if (idx == off - 1) nsrc = dst;     // self-loop slot
            int m = min(32, end - base);
            for (int e = 0; e < m; e++) {
                int src = __shfl_sync(0xffffffffu, nsrc, e);
                const float4* xls = (const float4*)(g_xl + (size_t)src * D);
                float4 a0 = xls[lane], a1 = xls[lane + 32];
                float s, p;
                s = a0.x + r0.x; p  = t0.x * lrelu(s);
                s = a0.y + r0.y; p += t0.y * lrelu(s);
                s = a0.z + r0.z; p += t0.z * lrelu(s);
                s = a0.w + r0.w; p += t0.w * lrelu(s);
                s = a1.x + r1.x; p += t1.x * lrelu(s);
                s = a1.y + r1.y; p += t1.y * lrelu(s);
                s = a1.z + r1.z; p += t1.z * lrelu(s);
                s = a1.w + r1.w; p += t1.w * lrelu(s);
#pragma unroll
                for (int o = 16; o; o >>= 1) p += __shfl_xor_sync(0xffffffffu, p, o);
                float ev = __expf(p);
                den += ev;
                acc0.x += ev * a0.x; acc0.y += ev * a0.y;
                acc0.z += ev * a0.z; acc0.w += ev * a0.w;
                acc1.x += ev * a1.x; acc1.y += ev * a1.y;
                acc1.z += ev * a1.z; acc1.w += ev * a1.w;
            }
        }

        float inv = 1.f / den;
        const float4* dup = (const float4*)(du + (size_t)dst * D);
        float4 u0 = dup[lane], u1 = dup[lane + 32];
        const float4* bp = (const float4*)bias;
        float4 b0 = bp[lane], b1 = bp[lane + 32];

        float4 v0, v1;
        v0.x = fmaxf(acc0.x * inv + b0.x, 0.f); v0.x = (u0.x >= 0.5f) ? v0.x * 2.f : 0.f;
        v0.y = fmaxf(acc0.y * inv + b0.y, 0.f); v0.y = (u0.y >= 0.5f) ? v0.y * 2.f : 0.f;
        v0.z = fmaxf(acc0.z * inv + b0.z, 0.f); v0.z = (u0.z >= 0.5f) ? v0.z * 2.f : 0.f;
        v0.w = fmaxf(acc0.w * inv + b0.w, 0.f); v0.w = (u0.w >= 0.5f) ? v0.w * 2.f : 0.f;
        v1.x = fmaxf(acc1.x * inv + b1.x, 0.f); v1.x = (u1.x >= 0.5f) ? v1.x * 2.f : 0.f;
        v1.y = fmaxf(acc1.y * inv + b1.y, 0.f); v1.y = (u1.y >= 0.5f) ? v1.y * 2.f : 0.f;
        v1.z = fmaxf(acc1.z * inv + b1.z, 0.f); v1.z = (u1.z >= 0.5f) ? v1.z * 2.f : 0.f;
        v1.w = fmaxf(acc1.w * inv + b1.w, 0.f); v1.w = (u1.w >= 0.5f) ? v1.w * 2.f : 0.f;

        float4* op = (float4*)(g_agg + (size_t)dst * D);
        op[lane] = v0; op[lane + 32] = v1;

        int c0 = lane * 4, c1 = 128 + lane * 4;
        atomicAdd(&s_sum[c0 + 0], v0.x); atomicAdd(&s_sq[c0 + 0], v0.x * v0.x);
        atomicAdd(&s_sum[c0 + 1], v0.y); atomicAdd(&s_sq[c0 + 1], v0.y * v0.y);
        atomicAdd(&s_sum[c0 + 2], v0.z); atomicAdd(&s_sq[c0 + 2], v0.z * v0.z);
        atomicAdd(&s_sum[c0 + 3], v0.w); atomicAdd(&s_sq[c0 + 3], v0.w * v0.w);
        atomicAdd(&s_sum[c1 + 0], v1.x); atomicAdd(&s_sq[c1 + 0], v1.x * v1.x);
        atomicAdd(&s_sum[c1 + 1], v1.y); atomicAdd(&s_sq[c1 + 1], v1.y * v1.y);
        atomicAdd(&s_sum[c1 + 2], v1.z); atomicAdd(&s_sq[c1 + 2], v1.z * v1.z);
        atomicAdd(&s_sum[c1 + 3], v1.w); atomicAdd(&s_sq[c1 + 3], v1.w * v1.w);
    }
    __syncthreads();
    atomicAdd(&g_colsum[tid], s_sum[tid]);
    atomicAdd(&g_colsumsq[tid], s_sq[tid]);
}

// ---------------- final BN normalize --------------------------------
__global__ void k_bnnorm(const float* __restrict__ gamma, const float* __restrict__ beta,
                         float* __restrict__ out, int N) {
    int d = threadIdx.x;
    float invN = 1.f / (float)N;
    float mean = g_colsum[d] * invN;
    float var = g_colsumsq[d] * invN - mean * mean;
    float inv = rsqrtf(var + 1e-5f);
    float ga = gamma[d], be = beta[d];
    for (int r = blockIdx.x; r < N; r += gridDim.x) {
        out[(size_t)r * D + d] = ga * (g_agg[(size_t)r * D + d] - mean) * inv + be;
    }
}

// ---------------- launch ---------------------------------------------
extern "C" void kernel_launch(void* const* d_in, const int* in_sizes, int n_in,
                              void* d_out, int out_size) {
    (void)n_in; (void)out_size;
    const float* x     = (const float*)d_in[0];
    const void*  ei    = d_in[1];
    const float* Wl    = (const float*)d_in[2];
    const float* bl    = (const float*)d_in[3];
    const float* Wr    = (const float*)d_in[4];
    const float* br    = (const float*)d_in[5];
    const float* att   = (const float*)d_in[6];
    const float* bias  = (const float*)d_in[7];
    const float* gamma = (const float*)d_in[8];
    const float* beta  = (const float*)d_in[9];
    const float* du    = (const float*)d_in[10];

    int N = in_sizes[0] / D;
    int E = in_sizes[1] / 2;
    int mrows = (N + 127) / 128;
    int NPAD = mrows * 128;

    const int SMEM_MMA = 2 * SMSTAGE;   // 147456 bytes
    static int smem_set = 0;
    if (!smem_set) {
        cudaFuncSetAttribute(k_hmma, cudaFuncAttributeMaxDynamicSharedMemorySize, SMEM_MMA);
        smem_set = 1;
    }

    // init + dtype detect (one kernel)
    k_init<<<40, 256>>>((const long long*)ei, E, N);

    // CSR build: count -> unordered alloc -> fill
    k_count<<<(E + 255) / 256, 256>>>(ei, E);
    k_alloc<<<(N + 255) / 256, 256>>>(N);
    k_fill<<<(E + 255) / 256, 256>>>(ei, E);

    // bf16 split conversions
    int convx_threads = NPAD * (D / 4);
    k_conv_x<<<(convx_threads + 255) / 256, 256>>>(x, N, NPAD);
    dim3 gw(16, 8);
    k_conv_w<<<gw, 256>>>(Wl, Wr);

    // fused dual GEMM
    dim3 gg(4, mrows);
    k_hmma<<<gg, 256, SMEM_MMA>>>(bl, br, N);

    // dst-centric aggregation + epilogue + BN stats
    k_agg<<<(N + 7) / 8, 256>>>(att, bias, du, N);

    // BN normalize
    k_bnnorm<<<512, 256>>>(gamma, beta, (float*)d_out, N);
}

// round 6
// speedup vs baseline: 1.6736x; 1.0257x over previous
#include <cuda_runtime.h>
#include <cuda_bf16.h>
#include <cstdint>

#define NMAXP 10240          // padded row capacity (N=10000 -> 79*128=10112)
#define D 256
#define EMAX 200000

// ---------------- scratch (no allocation allowed) ----------------
__device__ float g_xl[NMAXP * D];
__device__ float g_xr[NMAXP * D];
__device__ float g_agg[NMAXP * D];
__device__ float g_colsum[D];
__device__ float g_colsumsq[D];
__device__ int   g_is32;
__device__ int   g_total;
// CSR by destination (unordered base allocation)
__device__ int g_deg[NMAXP];
__device__ int g_off[NMAXP];
__device__ int g_cur[NMAXP];
__device__ int g_csr_src[EMAX];
// bf16 split operands
__device__ __nv_bfloat16 g_ah[NMAXP * D];
__device__ __nv_bfloat16 g_al[NMAXP * D];
__device__ __nv_bfloat16 g_bh[512 * D];   // B[n][k] = W[k][n], n in [0,512)
__device__ __nv_bfloat16 g_bl[512 * D];

__device__ __forceinline__ float lrelu(float s) { return s > 0.f ? s : 0.2f * s; }

// ================= helpers =========================================
__device__ __forceinline__ uint32_t smem_u32(const void* p) {
    uint32_t a;
    asm("{ .reg .u64 t; cvta.to.shared.u64 t, %1; cvt.u32.u64 %0, t; }" : "=r"(a) : "l"(p));
    return a;
}
__device__ __forceinline__ void ldsm_x4(uint32_t& r0, uint32_t& r1, uint32_t& r2,
                                        uint32_t& r3, uint32_t a) {
    asm volatile("ldmatrix.sync.aligned.m8n8.x4.shared.b16 {%0,%1,%2,%3}, [%4];"
                 : "=r"(r0), "=r"(r1), "=r"(r2), "=r"(r3) : "r"(a));
}
__device__ __forceinline__ void mma_bf16(float* d, const uint32_t* a, const uint32_t* b) {
    asm volatile(
        "mma.sync.aligned.m16n8k16.row.col.f32.bf16.bf16.f32 "
        "{%0,%1,%2,%3},{%4,%5,%6,%7},{%8,%9},{%0,%1,%2,%3};"
        : "+f"(d[0]), "+f"(d[1]), "+f"(d[2]), "+f"(d[3])
        : "r"(a[0]), "r"(a[1]), "r"(a[2]), "r"(a[3]), "r"(b[0]), "r"(b[1]));
}
__device__ __forceinline__ void cpasync16(uint32_t dst, const void* src) {
    asm volatile("{ .reg .u64 g; cvta.to.global.u64 g, %1;"
                 "  cp.async.cg.shared.global [%0], [g], 16; }"
                 :: "r"(dst), "l"(src) : "memory");
}

// ---------------- init: zero counters + detect dtype ----------------
__global__ void k_init(const long long* ei, int E, int N) {
    int tid = blockIdx.x * blockDim.x + threadIdx.x;
    int stride = gridDim.x * blockDim.x;
    for (int i = tid; i < N; i += stride) g_deg[i] = 0;
    if (blockIdx.x == 0) {
        if (threadIdx.x < D) {
            g_colsum[threadIdx.x] = 0.f;
            g_colsumsq[threadIdx.x] = 0.f;
        }
        if (threadIdx.x == 0) g_total = 0;
    }
    if (blockIdx.x == 1) {
        int bad = 0;
        int lim = E < 2048 ? E : 2048;
        for (int i = threadIdx.x; i < lim; i += blockDim.x) {
            long long v = ei[i];
            if (v < 0 || v >= (long long)N) bad = 1;
        }
        int any = __syncthreads_or(bad);
        if (threadIdx.x == 0) g_is32 = any ? 1 : 0;
    }
}

// ---------------- CSR build: count (4 edges/thread) -----------------
__global__ void k_count(const void* __restrict__ ei, int E) {
    int i0 = (blockIdx.x * blockDim.x + threadIdx.x) * 4;
    if (i0 >= E) return;
    int is32 = g_is32;
    int d[4];
    int m = min(4, E - i0);
#pragma unroll
    for (int j = 0; j < 4; j++) {
        if (j < m)
            d[j] = is32 ? __ldg((const int*)ei + E + i0 + j)
                        : (int)__ldg((const long long*)ei + E + i0 + j);
    }
#pragma unroll
    for (int j = 0; j < 4; j++)
        if (j < m) atomicAdd(&g_deg[d[j]], 1);
}

// ---------------- CSR build: unordered base allocation ---------------
// Warp-aggregated atomicAdd on one counter; segment order is irrelevant
// because the aggregation is commutative.
__global__ void k_alloc(int N) {
    int i = blockIdx.x * blockDim.x + threadIdx.x;
    int lane = threadIdx.x & 31;
    int d = (i < N) ? g_deg[i] : 0;
    int p = d;
#pragma unroll
    for (int o = 1; o < 32; o <<= 1) {
        int t = __shfl_up_sync(0xffffffffu, p, o);
        if (lane >= o) p += t;
    }
    int total = __shfl_sync(0xffffffffu, p, 31);
    int base = 0;
    if (lane == 0) base = atomicAdd(&g_total, total);
    base = __shfl_sync(0xffffffffu, base, 0);
    int off = base + p - d;
    if (i < N) {
        g_off[i] = off;
        g_cur[i] = off;
    }
}

// ---------------- CSR build: fill (4 edges/thread) -------------------
__global__ void k_fill(const void* __restrict__ ei, int E) {
    int i0 = (blockIdx.x * blockDim.x + threadIdx.x) * 4;
    if (i0 >= E) return;
    int is32 = g_is32;
    int m = min(4, E - i0);
    int s[4], d[4], pos[4];
#pragma unroll
    for (int j = 0; j < 4; j++) {
        if (j < m) {
            if (is32) {
                s[j] = __ldg((const int*)ei + i0 + j);
                d[j] = __ldg((const int*)ei + E + i0 + j);
            } else {
                s[j] = (int)__ldg((const long long*)ei + i0 + j);
                d[j] = (int)__ldg((const long long*)ei + E + i0 + j);
            }
        }
    }
#pragma unroll
    for (int j = 0; j < 4; j++)
        if (j < m) pos[j] = atomicAdd(&g_cur[d[j]], 1);
#pragma unroll
    for (int j = 0; j < 4; j++)
        if (j < m) g_csr_src[pos[j]] = s[j];
}

// ---------------- fp32 -> bf16 hi/lo split of x (padded rows = 0) --
__global__ void k_conv_x(const float* __restrict__ x, int N, int NPAD) {
    int gid = blockIdx.x * blockDim.x + threadIdx.x;   // one per 4 elements
    int total = NPAD * (D / 4);
    if (gid >= total) return;
    int base = gid * 4;
    int r = base >> 8;
    float4 v = (r < N) ? *(const float4*)(x + base) : make_float4(0.f, 0.f, 0.f, 0.f);
    __nv_bfloat16 h0 = __float2bfloat16(v.x), h1 = __float2bfloat16(v.y);
    __nv_bfloat16 h2 = __float2bfloat16(v.z), h3 = __float2bfloat16(v.w);
    __nv_bfloat16 l0 = __float2bfloat16(v.x - __bfloat162float(h0));
    __nv_bfloat16 l1 = __float2bfloat16(v.y - __bfloat162float(h1));
    __nv_bfloat16 l2 = __float2bfloat16(v.z - __bfloat162float(h2));
    __nv_bfloat16 l3 = __float2bfloat16(v.w - __bfloat162float(h3));
    __nv_bfloat162* ph = (__nv_bfloat162*)(g_ah + base);
    __nv_bfloat162* pl = (__nv_bfloat162*)(g_al + base);
    ph[0] = __nv_bfloat162(h0, h1); ph[1] = __nv_bfloat162(h2, h3);
    pl[0] = __nv_bfloat162(l0, l1); pl[1] = __nv_bfloat162(l2, l3);
}

// ---------------- W transpose via smem tiles: B[n][k] = W[k][n] -----
__global__ void k_conv_w(const float* __restrict__ Wl, const float* __restrict__ Wr) {
    __shared__ __nv_bfloat16 sh[32][33];
    __shared__ __nv_bfloat16 sl[32][33];
    int n0 = blockIdx.x * 32;
    int k0 = blockIdx.y * 32;
    int tid = threadIdx.x;
    int c = tid & 31;
    int r = tid >> 5;
#pragma unroll
    for (int i = 0; i < 4; i++) {
        int k = r + i * 8;
        int n = n0 + c;
        float v = (n < 256) ? Wl[(size_t)(k0 + k) * 256 + n]
                            : Wr[(size_t)(k0 + k) * 256 + (n - 256)];
        __nv_bfloat16 h = __float2bfloat16(v);
        sh[k][c] = h;
        sl[k][c] = __float2bfloat16(v - __bfloat162float(h));
    }
    __syncthreads();
    int nn = tid >> 4;
    int kk = (tid & 15) * 2;
#pragma unroll
    for (int i = 0; i < 2; i++) {
        int nl = nn + i * 16;
        int n = n0 + nl;
        *(__nv_bfloat162*)&g_bh[(size_t)n * D + k0 + kk] = __nv_bfloat162(sh[kk][nl], sh[kk + 1][nl]);
        *(__nv_bfloat162*)&g_bl[(size_t)n * D + k0 + kk] = __nv_bfloat162(sl[kk][nl], sl[kk + 1][nl]);
    }
}

// ---------------- HMMA 3xBF16 fused GEMM ----------------------------
#define SMSTRIDE 144
#define SMARR    (128 * SMSTRIDE)
#define SMSTAGE  (4 * SMARR)

__global__ void __launch_bounds__(256, 1)
k_hmma(const float* __restrict__ bl, const float* __restrict__ br, int N) {
    extern __shared__ char sm[];
    uint32_t sb = smem_u32(sm);
    const int tid = threadIdx.x, lane = tid & 31, warp = tid >> 5;
    const int wm = warp >> 1, wn = warp & 1;
    const int row0 = blockIdx.y * 128;
    const int ncol0 = blockIdx.x * 128;

    float acc[2][8][4];
#pragma unroll
    for (int mt = 0; mt < 2; mt++)
#pragma unroll
        for (int nt = 0; nt < 8; nt++)
#pragma unroll
            for (int i = 0; i < 4; i++) acc[mt][nt][i] = 0.f;

    auto issue = [&](int c) {
        uint32_t s0 = sb + (c & 1) * SMSTAGE;
        int kc = c * 64;
#pragma unroll
        for (int i = 0; i < 4; i++) {
            int idx = tid + i * 256;
            int r = idx >> 3, g = idx & 7;
            uint32_t doff = (uint32_t)(r * SMSTRIDE + g * 16);
            size_t aoff = (size_t)(row0 + r) * D + kc + g * 8;
            size_t boff = (size_t)(ncol0 + r) * D + kc + g * 8;
            cpasync16(s0 + doff,              g_ah + aoff);
            cpasync16(s0 + SMARR + doff,      g_al + aoff);
            cpasync16(s0 + 2 * SMARR + doff,  g_bh + boff);
            cpasync16(s0 + 3 * SMARR + doff,  g_bl + boff);
        }
        asm volatile("cp.async.commit_group;" ::: "memory");
    };

    issue(0);
    for (int c = 0; c < 4; c++) {
        if (c < 3) {
            issue(c + 1);
            asm volatile("cp.async.wait_group 1;" ::: "memory");
        } else {
            asm volatile("cp.async.wait_group 0;" ::: "memory");
        }
        __syncthreads();

        uint32_t s0 = sb + (c & 1) * SMSTAGE;
        uint32_t aoffB = (uint32_t)((wm * 32 + (lane & 15)) * SMSTRIDE + (lane >> 4) * 16);
        uint32_t nsel = (uint32_t)(lane >> 4);
        uint32_t nloc = (uint32_t)(lane & 7);
        uint32_t khalf = (uint32_t)((lane >> 3) & 1);

#pragma unroll
        for (int kt = 0; kt < 4; kt++) {
            uint32_t kb = kt * 32;
            uint32_t ah[2][4], al[2][4];
#pragma unroll
            for (int mt = 0; mt < 2; mt++) {
                uint32_t adr = s0 + aoffB + mt * 16 * SMSTRIDE + kb;
                ldsm_x4(ah[mt][0], ah[mt][1], ah[mt][2], ah[mt][3], adr);
                ldsm_x4(al[mt][0], al[mt][1], al[mt][2], al[mt][3], adr + SMARR);
            }
            uint32_t bh[4][4], blo[4][4];
#pragma unroll
            for (int p = 0; p < 4; p++) {
                uint32_t n = (uint32_t)(wn * 64) + (2 * p + nsel) * 8 + nloc;
                uint32_t adr = s0 + 2 * SMARR + n * SMSTRIDE + kb + khalf * 16;
                ldsm_x4(bh[p][0], bh[p][1], bh[p][2], bh[p][3], adr);
                ldsm_x4(blo[p][0], blo[p][1], blo[p][2], blo[p][3], adr + SMARR);
            }
#pragma unroll
            for (int mt = 0; mt < 2; mt++)
#pragma unroll
                for (int nt = 0; nt < 8; nt++) {
                    const uint32_t* bhp = &bh[nt >> 1][(nt & 1) * 2];
                    const uint32_t* blp = &blo[nt >> 1][(nt & 1) * 2];
                    mma_bf16(acc[mt][nt], ah[mt], bhp);
                    mma_bf16(acc[mt][nt], al[mt], bhp);
                    mma_bf16(acc[mt][nt], ah[mt], blp);
                }
        }
        __syncthreads();
    }

    const float* bsel = (blockIdx.x < 2) ? bl : br;
    float* Cout = (blockIdx.x < 2) ? g_xl : g_xr;
    int colbase = (blockIdx.x & 1) * 128 + wn * 64;
#pragma unroll
    for (int mt = 0; mt < 2; mt++) {
        int r0 = row0 + wm * 32 + mt * 16 + (lane >> 2);
#pragma unroll
        for (int nt = 0; nt < 8; nt++) {
            int cc = colbase + nt * 8 + (lane & 3) * 2;
            float b0 = bsel[cc], b1 = bsel[cc + 1];
            if (r0 < N) {
                float2 v = make_float2(acc[mt][nt][0] + b0, acc[mt][nt][1] + b1);
                *(float2*)&Cout[(size_t)r0 * D + cc] = v;
            }
            if (r0 + 8 < N) {
                float2 v = make_float2(acc[mt][nt][2] + b0, acc[mt][nt][3] + b1);
                *(float2*)&Cout[(size_t)(r0 + 8) * D + cc] = v;
            }
        }
    }
}

// ---------------- dst-centric aggregation + epilogue -----------------
__global__ void __launch_bounds__(256)
k_agg(const float* __restrict__ att, const float* __restrict__ bias,
      const float* __restrict__ du, int N) {
    __shared__ float s_sum[D];
    __shared__ float s_sq[D];
    int tid = threadIdx.x, warp = tid >> 5, lane = tid & 31;
    for (int i = tid; i < D; i += 256) { s_sum[i] = 0.f; s_sq[i] = 0.f; }
    __syncthreads();

    int dst = blockIdx.x * 8 + warp;
    if (dst < N) {
        const float4* xrd = (const float4*)(g_xr + (size_t)dst * D);
        float4 r0 = xrd[lane], r1 = xrd[lane + 32];
        float4 t0 = ((const float4*)att)[lane];
        float4 t1 = ((const float4*)att)[lane + 32];

        float4 acc0 = make_float4(0.f, 0.f, 0.f, 0.f);
        float4 acc1 = make_float4(0.f, 0.f, 0.f, 0.f);
        float den = 0.f;

        int off = g_off[dst];
        int end = g_cur[dst];           // after k_fill, cur == off + deg

        // process self-loop (src = dst) + CSR edges
        for (int base = off - 1; base < end; base += 32) {
            int nsrc = -1;
            int idx = base + lane;
            if (idx >= off && idx < end) nsrc = g_csr_src[idx];
            else if (idx == off - 1) nsrc = dst;     // self-loop slot
            int m = min(32, end - base);
            for (int e = 0; e < m; e++) {
                int src = __shfl_sync(0xffffffffu, nsrc, e);
                const float4* xls = (const float4*)(g_xl + (size_t)src * D);
                float4 a0 = xls[lane], a1 = xls[lane + 32];
                float s, p;
                s = a0.x + r0.x; p  = t0.x * lrelu(s);
                s = a0.y + r0.y; p += t0.y * lrelu(s);
                s = a0.z + r0.z; p += t0.z * lrelu(s);
                s = a0.w + r0.w; p += t0.w * lrelu(s);
                s = a1.x + r1.x; p += t1.x * lrelu(s);
                s = a1.y + r1.y; p += t1.y * lrelu(s);
                s = a1.z + r1.z; p += t1.z * lrelu(s);
                s = a1.w + r1.w; p += t1.w * lrelu(s);
#pragma unroll
                for (int o = 16; o; o >>= 1) p += __shfl_xor_sync(0xffffffffu, p, o);
                float ev = __expf(p);
                den += ev;
                acc0.x += ev * a0.x; acc0.y += ev * a0.y;
                acc0.z += ev * a0.z; acc0.w += ev * a0.w;
                acc1.x += ev * a1.x; acc1.y += ev * a1.y;
                acc1.z += ev * a1.z; acc1.w += ev * a1.w;
            }
        }

        float inv = 1.f / den;
        const float4* dup = (const float4*)(du + (size_t)dst * D);
        float4 u0 = dup[lane], u1 = dup[lane + 32];
        const float4* bp = (const float4*)bias;
        float4 b0 = bp[lane], b1 = bp[lane + 32];

        float4 v0, v1;
        v0.x = fmaxf(acc0.x * inv + b0.x, 0.f); v0.x = (u0.x >= 0.5f) ? v0.x * 2.f : 0.f;
        v0.y = fmaxf(acc0.y * inv + b0.y, 0.f); v0.y = (u0.y >= 0.5f) ? v0.y * 2.f : 0.f;
        v0.z = fmaxf(acc0.z * inv + b0.z, 0.f); v0.z = (u0.z >= 0.5f) ? v0.z * 2.f : 0.f;
        v0.w = fmaxf(acc0.w * inv + b0.w, 0.f); v0.w = (u0.w >= 0.5f) ? v0.w * 2.f : 0.f;
        v1.x = fmaxf(acc1.x * inv + b1.x, 0.f); v1.x = (u1.x >= 0.5f) ? v1.x * 2.f : 0.f;
        v1.y = fmaxf(acc1.y * inv + b1.y, 0.f); v1.y = (u1.y >= 0.5f) ? v1.y * 2.f : 0.f;
        v1.z = fmaxf(acc1.z * inv + b1.z, 0.f); v1.z = (u1.z >= 0.5f) ? v1.z * 2.f : 0.f;
        v1.w = fmaxf(acc1.w * inv + b1.w, 0.f); v1.w = (u1.w >= 0.5f) ? v1.w * 2.f : 0.f;

        float4* op = (float4*)(g_agg + (size_t)dst * D);
        op[lane] = v0; op[lane + 32] = v1;

        int c0 = lane * 4, c1 = 128 + lane * 4;
        atomicAdd(&s_sum[c0 + 0], v0.x); atomicAdd(&s_sq[c0 + 0], v0.x * v0.x);
        atomicAdd(&s_sum[c0 + 1], v0.y); atomicAdd(&s_sq[c0 + 1], v0.y * v0.y);
        atomicAdd(&s_sum[c0 + 2], v0.z); atomicAdd(&s_sq[c0 + 2], v0.z * v0.z);
        atomicAdd(&s_sum[c0 + 3], v0.w); atomicAdd(&s_sq[c0 + 3], v0.w * v0.w);
        atomicAdd(&s_sum[c1 + 0], v1.x); atomicAdd(&s_sq[c1 + 0], v1.x * v1.x);
        atomicAdd(&s_sum[c1 + 1], v1.y); atomicAdd(&s_sq[c1 + 1], v1.y * v1.y);
        atomicAdd(&s_sum[c1 + 2], v1.z); atomicAdd(&s_sq[c1 + 2], v1.z * v1.z);
        atomicAdd(&s_sum[c1 + 3], v1.w); atomicAdd(&s_sq[c1 + 3], v1.w * v1.w);
    }
    __syncthreads();
    atomicAdd(&g_colsum[tid], s_sum[tid]);
    atomicAdd(&g_colsumsq[tid], s_sq[tid]);
}

// ---------------- final BN normalize --------------------------------
__global__ void k_bnnorm(const float* __restrict__ gamma, const float* __restrict__ beta,
                         float* __restrict__ out, int N) {
    int d = threadIdx.x;
    float invN = 1.f / (float)N;
    float mean = g_colsum[d] * invN;
    float var = g_colsumsq[d] * invN - mean * mean;
    float inv = rsqrtf(var + 1e-5f);
    float ga = gamma[d], be = beta[d];
    for (int r = blockIdx.x; r < N; r += gridDim.x) {
        out[(size_t)r * D + d] = ga * (g_agg[(size_t)r * D + d] - mean) * inv + be;
    }
}

// ---------------- launch ---------------------------------------------
extern "C" void kernel_launch(void* const* d_in, const int* in_sizes, int n_in,
                              void* d_out, int out_size) {
    (void)n_in; (void)out_size;
    const float* x     = (const float*)d_in[0];
    const void*  ei    = d_in[1];
    const float* Wl    = (const float*)d_in[2];
    const float* bl    = (const float*)d_in[3];
    const float* Wr    = (const float*)d_in[4];
    const float* br    = (const float*)d_in[5];
    const float* att   = (const float*)d_in[6];
    const float* bias  = (const float*)d_in[7];
    const float* gamma = (const float*)d_in[8];
    const float* beta  = (const float*)d_in[9];
    const float* du    = (const float*)d_in[10];

    int N = in_sizes[0] / D;
    int E = in_sizes[1] / 2;
    int mrows = (N + 127) / 128;
    int NPAD = mrows * 128;

    const int SMEM_MMA = 2 * SMSTAGE;   // 147456 bytes
    static cudaStream_t s2 = nullptr;
    static cudaEvent_t evFork = nullptr, evJoin = nullptr;
    if (!s2) {
        cudaFuncSetAttribute(k_hmma, cudaFuncAttributeMaxDynamicSharedMemorySize, SMEM_MMA);
        cudaStreamCreateWithFlags(&s2, cudaStreamNonBlocking);
        cudaEventCreateWithFlags(&evFork, cudaEventDisableTiming);
        cudaEventCreateWithFlags(&evJoin, cudaEventDisableTiming);
    }

    // ---- fork: CSR chain on s2, GEMM chain on main stream ----
    cudaEventRecord(evFork, 0);
    cudaStreamWaitEvent(s2, evFork, 0);

    // branch B (s2): init + dtype detect -> count -> alloc -> fill
    k_init<<<40, 256, 0, s2>>>((const long long*)ei, E, N);
    k_count<<<(E / 4 + 256) / 256, 256, 0, s2>>>(ei, E);
    k_alloc<<<(N + 255) / 256, 256, 0, s2>>>(N);
    k_fill<<<(E / 4 + 256) / 256, 256, 0, s2>>>(ei, E);
    cudaEventRecord(evJoin, s2);

    // branch A (main): bf16 conversions -> fused dual GEMM
    int convx_threads = NPAD * (D / 4);
    k_conv_x<<<(convx_threads + 255) / 256, 256>>>(x, N, NPAD);
    dim3 gw(16, 8);
    k_conv_w<<<gw, 256>>>(Wl, Wr);
    dim3 gg(4, mrows);
    k_hmma<<<gg, 256, SMEM_MMA>>>(bl, br, N);

    // ---- join ----
    cudaStreamWaitEvent(0, evJoin, 0);

    // dst-centric aggregation + epilogue + BN stats
    k_agg<<<(N + 7) / 8, 256>>>(att, bias, du, N);

    // BN normalize
    k_bnnorm<<<512, 256>>>(gamma, beta, (float*)d_out, N);
}

// round 7
// speedup vs baseline: 1.6846x; 1.0066x over previous
#include <cuda_runtime.h>
#include <cuda_bf16.h>
#include <cstdint>

#define NMAXP 10240          // padded row capacity (N=10000 -> 79*128=10112)
#define D 256
#define EMAX 200000

// ---------------- scratch (no allocation allowed) ----------------
__device__ float g_xl[NMAXP * D];
__device__ float g_xr[NMAXP * D];
__device__ float g_agg[NMAXP * D];
__device__ float g_colsum[D];
__device__ float g_colsumsq[D];
__device__ int   g_is32;
__device__ int   g_total;
// CSR by destination (unordered base allocation)
__device__ int g_deg[NMAXP];
__device__ int g_off[NMAXP];
__device__ int g_cur[NMAXP];
__device__ int g_csr_src[EMAX];
// bf16 split operands
__device__ __nv_bfloat16 g_ah[NMAXP * D];
__device__ __nv_bfloat16 g_al[NMAXP * D];
__device__ __nv_bfloat16 g_bh[512 * D];   // B[n][k] = W[k][n], n in [0,512)
__device__ __nv_bfloat16 g_bl[512 * D];

__device__ __forceinline__ float lrelu(float s) { return s > 0.f ? s : 0.2f * s; }

// ================= helpers =========================================
__device__ __forceinline__ uint32_t smem_u32(const void* p) {
    uint32_t a;
    asm("{ .reg .u64 t; cvta.to.shared.u64 t, %1; cvt.u32.u64 %0, t; }" : "=r"(a) : "l"(p));
    return a;
}
__device__ __forceinline__ void ldsm_x4(uint32_t& r0, uint32_t& r1, uint32_t& r2,
                                        uint32_t& r3, uint32_t a) {
    asm volatile("ldmatrix.sync.aligned.m8n8.x4.shared.b16 {%0,%1,%2,%3}, [%4];"
                 : "=r"(r0), "=r"(r1), "=r"(r2), "=r"(r3) : "r"(a));
}
__device__ __forceinline__ void mma_bf16(float* d, const uint32_t* a, const uint32_t* b) {
    asm volatile(
        "mma.sync.aligned.m16n8k16.row.col.f32.bf16.bf16.f32 "
        "{%0,%1,%2,%3},{%4,%5,%6,%7},{%8,%9},{%0,%1,%2,%3};"
        : "+f"(d[0]), "+f"(d[1]), "+f"(d[2]), "+f"(d[3])
        : "r"(a[0]), "r"(a[1]), "r"(a[2]), "r"(a[3]), "r"(b[0]), "r"(b[1]));
}
__device__ __forceinline__ void cpasync16(uint32_t dst, const void* src) {
    asm volatile("{ .reg .u64 g; cvta.to.global.u64 g, %1;"
                 "  cp.async.cg.shared.global [%0], [g], 16; }"
                 :: "r"(dst), "l"(src) : "memory");
}

// ---------------- init: zero counters + detect dtype ----------------
__global__ void k_init(const long long* ei, int E, int N) {
    int tid = blockIdx.x * blockDim.x + threadIdx.x;
    int stride = gridDim.x * blockDim.x;
    for (int i = tid; i < N; i += stride) g_deg[i] = 0;
    if (blockIdx.x == 0) {
        if (threadIdx.x < D) {
            g_colsum[threadIdx.x] = 0.f;
            g_colsumsq[threadIdx.x] = 0.f;
        }
        if (threadIdx.x == 0) g_total = 0;
    }
    if (blockIdx.x == 1) {
        int bad = 0;
        int lim = E < 2048 ? E : 2048;
        for (int i = threadIdx.x; i < lim; i += blockDim.x) {
            long long v = ei[i];
            if (v < 0 || v >= (long long)N) bad = 1;
        }
        int any = __syncthreads_or(bad);
        if (threadIdx.x == 0) g_is32 = any ? 1 : 0;
    }
}

// ---------------- CSR build: count (2 edges/thread) -----------------
__global__ void k_count(const void* __restrict__ ei, int E) {
    int i0 = (blockIdx.x * blockDim.x + threadIdx.x) * 2;
    if (i0 >= E) return;
    int is32 = g_is32;
    int m = min(2, E - i0);
    int d[2];
#pragma unroll
    for (int j = 0; j < 2; j++)
        if (j < m)
            d[j] = is32 ? __ldg((const int*)ei + E + i0 + j)
                        : (int)__ldg((const long long*)ei + E + i0 + j);
#pragma unroll
    for (int j = 0; j < 2; j++)
        if (j < m) atomicAdd(&g_deg[d[j]], 1);
}

// ---------------- CSR build: unordered base allocation ---------------
__global__ void k_alloc(int N) {
    int i = blockIdx.x * blockDim.x + threadIdx.x;
    int lane = threadIdx.x & 31;
    int d = (i < N) ? g_deg[i] : 0;
    int p = d;
#pragma unroll
    for (int o = 1; o < 32; o <<= 1) {
        int t = __shfl_up_sync(0xffffffffu, p, o);
        if (lane >= o) p += t;
    }
    int total = __shfl_sync(0xffffffffu, p, 31);
    int base = 0;
    if (lane == 0) base = atomicAdd(&g_total, total);
    base = __shfl_sync(0xffffffffu, base, 0);
    int off = base + p - d;
    if (i < N) {
        g_off[i] = off;
        g_cur[i] = off;
    }
}

// ---------------- CSR build: fill (2 edges/thread) -------------------
__global__ void k_fill(const void* __restrict__ ei, int E) {
    int i0 = (blockIdx.x * blockDim.x + threadIdx.x) * 2;
    if (i0 >= E) return;
    int is32 = g_is32;
    int m = min(2, E - i0);
    int s[2], d[2], pos[2];
#pragma unroll
    for (int j = 0; j < 2; j++) {
        if (j < m) {
            if (is32) {
                s[j] = __ldg((const int*)ei + i0 + j);
                d[j] = __ldg((const int*)ei + E + i0 + j);
            } else {
                s[j] = (int)__ldg((const long long*)ei + i0 + j);
                d[j] = (int)__ldg((const long long*)ei + E + i0 + j);
            }
        }
    }
#pragma unroll
    for (int j = 0; j < 2; j++)
        if (j < m) pos[j] = atomicAdd(&g_cur[d[j]], 1);
#pragma unroll
    for (int j = 0; j < 2; j++)
        if (j < m) g_csr_src[pos[j]] = s[j];
}

// ---------------- fp32 -> bf16 hi/lo split of x (padded rows = 0) --
__global__ void k_conv_x(const float* __restrict__ x, int N, int NPAD) {
    int gid = blockIdx.x * blockDim.x + threadIdx.x;
    int total = NPAD * (D / 4);
    if (gid >= total) return;
    int base = gid * 4;
    int r = base >> 8;
    float4 v = (r < N) ? *(const float4*)(x + base) : make_float4(0.f, 0.f, 0.f, 0.f);
    __nv_bfloat16 h0 = __float2bfloat16(v.x), h1 = __float2bfloat16(v.y);
    __nv_bfloat16 h2 = __float2bfloat16(v.z), h3 = __float2bfloat16(v.w);
    __nv_bfloat16 l0 = __float2bfloat16(v.x - __bfloat162float(h0));
    __nv_bfloat16 l1 = __float2bfloat16(v.y - __bfloat162float(h1));
    __nv_bfloat16 l2 = __float2bfloat16(v.z - __bfloat162float(h2));
    __nv_bfloat16 l3 = __float2bfloat16(v.w - __bfloat162float(h3));
    __nv_bfloat162* ph = (__nv_bfloat162*)(g_ah + base);
    __nv_bfloat162* pl = (__nv_bfloat162*)(g_al + base);
    ph[0] = __nv_bfloat162(h0, h1); ph[1] = __nv_bfloat162(h2, h3);
    pl[0] = __nv_bfloat162(l0, l1); pl[1] = __nv_bfloat162(l2, l3);
}

// ---------------- W transpose via smem tiles: B[n][k] = W[k][n] -----
__global__ void k_conv_w(const float* __restrict__ Wl, const float* __restrict__ Wr) {
    __shared__ __nv_bfloat16 sh[32][33];
    __shared__ __nv_bfloat16 sl[32][33];
    int n0 = blockIdx.x * 32;
    int k0 = blockIdx.y * 32;
    int tid = threadIdx.x;
    int c = tid & 31;
    int r = tid >> 5;
#pragma unroll
    for (int i = 0; i < 4; i++) {
        int k = r + i * 8;
        int n = n0 + c;
        float v = (n < 256) ? Wl[(size_t)(k0 + k) * 256 + n]
                            : Wr[(size_t)(k0 + k) * 256 + (n - 256)];
        __nv_bfloat16 h = __float2bfloat16(v);
        sh[k][c] = h;
        sl[k][c] = __float2bfloat16(v - __bfloat162float(h));
    }
    __syncthreads();
    int nn = tid >> 4;
    int kk = (tid & 15) * 2;
#pragma unroll
    for (int i = 0; i < 2; i++) {
        int nl = nn + i * 16;
        int n = n0 + nl;
        *(__nv_bfloat162*)&g_bh[(size_t)n * D + k0 + kk] = __nv_bfloat162(sh[kk][nl], sh[kk + 1][nl]);
        *(__nv_bfloat162*)&g_bl[(size_t)n * D + k0 + kk] = __nv_bfloat162(sl[kk][nl], sl[kk + 1][nl]);
    }
}

// ---------------- HMMA 3xBF16 fused GEMM ----------------------------
// CTA tile M=128 x N=256, 512 threads = 16 warps (4M x 4N), warp 32x64.
// K in 4 chunks of 64, cp.async double-buffered.
// Stage: Ah|Al (128 rows) + Bh|Bl (256 rows), 144B row stride.
#define SMSTRIDE 144
#define ASZ (128 * SMSTRIDE)            // 18432
#define BSZ (256 * SMSTRIDE)            // 36864
#define STG (2 * ASZ + 2 * BSZ)         // 110592
#define OFF_AH 0
#define OFF_AL ASZ
#define OFF_BH (2 * ASZ)
#define OFF_BL (2 * ASZ + BSZ)

__global__ void __launch_bounds__(512, 1)
k_hmma(const float* __restrict__ bl, const float* __restrict__ br, int N) {
    extern __shared__ char sm[];
    uint32_t sb = smem_u32(sm);
    const int tid = threadIdx.x, lane = tid & 31, warp = tid >> 5;
    const int wm = warp >> 2, wn = warp & 3;
    const int row0 = blockIdx.y * 128;
    const int ncol0 = blockIdx.x * 256;    // 0 -> xl, 256 -> xr

    float acc[2][8][4];
#pragma unroll
    for (int mt = 0; mt < 2; mt++)
#pragma unroll
        for (int nt = 0; nt < 8; nt++)
#pragma unroll
            for (int i = 0; i < 4; i++) acc[mt][nt][i] = 0.f;

    auto issue = [&](int c) {
        uint32_t s0 = sb + (c & 1) * STG;
        int kc = c * 64;
        // 768 rows x 8 16B-chunks = 6144 copies / 512 threads = 12 each
#pragma unroll
        for (int i = 0; i < 12; i++) {
            int idx = tid + i * 512;
            int r = idx >> 3, g = idx & 7;
            if (r < 256) {          // A rows (hi then lo)
                int ar = r & 127;
                uint32_t dst = s0 + ((r < 128) ? OFF_AH : OFF_AL)
                             + (uint32_t)(ar * SMSTRIDE + g * 16);
                const __nv_bfloat16* srcb = (r < 128) ? g_ah : g_al;
                cpasync16(dst, srcb + (size_t)(row0 + ar) * D + kc + g * 8);
            } else {                // B rows (hi then lo)
                int br_ = (r - 256) & 255;
                uint32_t dst = s0 + ((r < 512) ? OFF_BH : OFF_BL)
                             + (uint32_t)(br_ * SMSTRIDE + g * 16);
                const __nv_bfloat16* srcb = (r < 512) ? g_bh : g_bl;
                cpasync16(dst, srcb + (size_t)(ncol0 + br_) * D + kc + g * 8);
            }
        }
        asm volatile("cp.async.commit_group;" ::: "memory");
    };

    issue(0);
    for (int c = 0; c < 4; c++) {
        if (c < 3) {
            issue(c + 1);
            asm volatile("cp.async.wait_group 1;" ::: "memory");
        } else {
            asm volatile("cp.async.wait_group 0;" ::: "memory");
        }
        __syncthreads();

        uint32_t s0 = sb + (c & 1) * STG;
        uint32_t aoffB = (uint32_t)((wm * 32 + (lane & 15)) * SMSTRIDE + (lane >> 4) * 16);
        uint32_t nsel = (uint32_t)(lane >> 4);
        uint32_t nloc = (uint32_t)(lane & 7);
        uint32_t khalf = (uint32_t)((lane >> 3) & 1);

#pragma unroll
        for (int kt = 0; kt < 4; kt++) {
            uint32_t kb = kt * 32;
            uint32_t ah[2][4], al[2][4];
#pragma unroll
            for (int mt = 0; mt < 2; mt++) {
                uint32_t adr = s0 + OFF_AH + aoffB + mt * 16 * SMSTRIDE + kb;
                ldsm_x4(ah[mt][0], ah[mt][1], ah[mt][2], ah[mt][3], adr);
                ldsm_x4(al[mt][0], al[mt][1], al[mt][2], al[mt][3], adr + ASZ);
            }
            uint32_t bh[4][4], blo[4][4];
#pragma unroll
            for (int p = 0; p < 4; p++) {
                uint32_t n = (uint32_t)(wn * 64) + (2 * p + nsel) * 8 + nloc;
                uint32_t adr = s0 + OFF_BH + n * SMSTRIDE + kb + khalf * 16;
                ldsm_x4(bh[p][0], bh[p][1], bh[p][2], bh[p][3], adr);
                ldsm_x4(blo[p][0], blo[p][1], blo[p][2], blo[p][3], adr + BSZ);
            }
#pragma unroll
            for (int mt = 0; mt < 2; mt++)
#pragma unroll
                for (int nt = 0; nt < 8; nt++) {
                    const uint32_t* bhp = &bh[nt >> 1][(nt & 1) * 2];
                    const uint32_t* blp = &blo[nt >> 1][(nt & 1) * 2];
                    mma_bf16(acc[mt][nt], ah[mt], bhp);
                    mma_bf16(acc[mt][nt], al[mt], bhp);
                    mma_bf16(acc[mt][nt], ah[mt], blp);
                }
        }
        __syncthreads();
    }

    const float* bsel = (blockIdx.x == 0) ? bl : br;
    float* Cout = (blockIdx.x == 0) ? g_xl : g_xr;
    int colbase = wn * 64;
#pragma unroll
    for (int mt = 0; mt < 2; mt++) {
        int r0 = row0 + wm * 32 + mt * 16 + (lane >> 2);
#pragma unroll
        for (int nt = 0; nt < 8; nt++) {
            int cc = colbase + nt * 8 + (lane & 3) * 2;
            float b0 = bsel[cc], b1 = bsel[cc + 1];
            if (r0 < N) {
                float2 v = make_float2(acc[mt][nt][0] + b0, acc[mt][nt][1] + b1);
                *(float2*)&Cout[(size_t)r0 * D + cc] = v;
            }
            if (r0 + 8 < N) {
                float2 v = make_float2(acc[mt][nt][2] + b0, acc[mt][nt][3] + b1);
                *(float2*)&Cout[(size_t)(r0 + 8) * D + cc] = v;
            }
        }
    }
}

// ---------------- dst-centric aggregation + epilogue -----------------
__global__ void __launch_bounds__(256)
k_agg(const float* __restrict__ att, const float* __restrict__ bias,
      const float* __restrict__ du, int N) {
    __shared__ float s_sum[D];
    __shared__ float s_sq[D];
    int tid = threadIdx.x, warp = tid >> 5, lane = tid & 31;
    for (int i = tid; i < D; i += 256) { s_sum[i] = 0.f; s_sq[i] = 0.f; }
    __syncthreads();

    int dst = blockIdx.x * 8 + warp;
    if (dst < N) {
        const float4* xrd = (const float4*)(g_xr + (size_t)dst * D);
        float4 r0 = xrd[lane], r1 = xrd[lane + 32];
        float4 t0 = ((const float4*)att)[lane];
        float4 t1 = ((const float4*)att)[lane + 32];

        float4 acc0 = make_float4(0.f, 0.f, 0.f, 0.f);
        float4 acc1 = make_float4(0.f, 0.f, 0.f, 0.f);
        float den = 0.f;

        int off = g_off[dst];
        int end = g_cur[dst];           // after k_fill, cur == off + deg

        for (int base = off - 1; base < end; base += 32) {
            int nsrc = -1;
            int idx = base + lane;
            if (idx >= off && idx < end) nsrc = g_csr_src[idx];
            else if (idx == off - 1) nsrc = dst;     // self-loop slot
            int m = min(32, end - base);
            int e = 0;
            // two independent edge pipelines to hide SHFL/L2 latency
            for (; e + 1 < m; e += 2) {
                int s0i = __shfl_sync(0xffffffffu, nsrc, e);
                int s1i = __shfl_sync(0xffffffffu, nsrc, e + 1);
                const float4* x0 = (const float4*)(g_xl + (size_t)s0i * D);
                const float4* x1 = (const float4*)(g_xl + (size_t)s1i * D);
                float4 a00 = x0[lane], a01 = x0[lane + 32];
                float4 a10 = x1[lane], a11 = x1[lane + 32];
                float p0, p1, s;
                s = a00.x + r0.x; p0  = t0.x * lrelu(s);
                s = a00.y + r0.y; p0 += t0.y * lrelu(s);
                s = a00.z + r0.z; p0 += t0.z * lrelu(s);
                s = a00.w + r0.w; p0 += t0.w * lrelu(s);
                s = a01.x + r1.x; p0 += t1.x * lrelu(s);
                s = a01.y + r1.y; p0 += t1.y * lrelu(s);
                s = a01.z + r1.z; p0 += t1.z * lrelu(s);
                s = a01.w + r1.w; p0 += t1.w * lrelu(s);
                s = a10.x + r0.x; p1  = t0.x * lrelu(s);
                s = a10.y + r0.y; p1 += t0.y * lrelu(s);
                s = a10.z + r0.z; p1 += t0.z * lrelu(s);
                s = a10.w + r0.w; p1 += t0.w * lrelu(s);
                s = a11.x + r1.x; p1 += t1.x * lrelu(s);
                s = a11.y + r1.y; p1 += t1.y * lrelu(s);
                s = a11.z + r1.z; p1 += t1.z * lrelu(s);
                s = a11.w + r1.w; p1 += t1.w * lrelu(s);
#pragma unroll
                for (int o = 16; o; o >>= 1) {
                    p0 += __shfl_xor_sync(0xffffffffu, p0, o);
                    p1 += __shfl_xor_sync(0xffffffffu, p1, o);
                }
                float ev0 = __expf(p0), ev1 = __expf(p1);
                den += ev0 + ev1;
                acc0.x += ev0 * a00.x + ev1 * a10.x;
                acc0.y += ev0 * a00.y + ev1 * a10.y;
                acc0.z += ev0 * a00.z + ev1 * a10.z;
                acc0.w += ev0 * a00.w + ev1 * a10.w;
                acc1.x += ev0 * a01.x + ev1 * a11.x;
                acc1.y += ev0 * a01.y + ev1 * a11.y;
                acc1.z += ev0 * a01.z + ev1 * a11.z;
                acc1.w += ev0 * a01.w + ev1 * a11.w;
            }
            if (e < m) {
                int src = __shfl_sync(0xffffffffu, nsrc, e);
                const float4* xls = (const float4*)(g_xl + (size_t)src * D);
                float4 a0 = xls[lane], a1 = xls[lane + 32];
                float s, p;
                s = a0.x + r0.x; p  = t0.x * lrelu(s);
                s = a0.y + r0.y; p += t0.y * lrelu(s);
                s = a0.z + r0.z; p += t0.z * lrelu(s);
                s = a0.w + r0.w; p += t0.w * lrelu(s);
                s = a1.x + r1.x; p += t1.x * lrelu(s);
                s = a1.y + r1.y; p += t1.y * lrelu(s);
                s = a1.z + r1.z; p += t1.z * lrelu(s);
                s = a1.w + r1.w; p += t1.w * lrelu(s);
#pragma unroll
                for (int o = 16; o; o >>= 1) p += __shfl_xor_sync(0xffffffffu, p, o);
                float ev = __expf(p);
                den += ev;
                acc0.x += ev * a0.x; acc0.y += ev * a0.y;
                acc0.z += ev * a0.z; acc0.w += ev * a0.w;
                acc1.x += ev * a1.x; acc1.y += ev * a1.y;
                acc1.z += ev * a1.z; acc1.w += ev * a1.w;
            }
        }

        float inv = 1.f / den;
        const float4* dup = (const float4*)(du + (size_t)dst * D);
        float4 u0 = dup[lane], u1 = dup[lane + 32];
        const float4* bp = (const float4*)bias;
        float4 b0 = bp[lane], b1 = bp[lane + 32];

        float4 v0, v1;
        v0.x = fmaxf(acc0.x * inv + b0.x, 0.f); v0.x = (u0.x >= 0.5f) ? v0.x * 2.f : 0.f;
        v0.y = fmaxf(acc0.y * inv + b0.y, 0.f); v0.y = (u0.y >= 0.5f) ? v0.y * 2.f : 0.f;
        v0.z = fmaxf(acc0.z * inv + b0.z, 0.f); v0.z = (u0.z >= 0.5f) ? v0.z * 2.f : 0.f;
        v0.w = fmaxf(acc0.w * inv + b0.w, 0.f); v0.w = (u0.w >= 0.5f) ? v0.w * 2.f : 0.f;
        v1.x = fmaxf(acc1.x * inv + b1.x, 0.f); v1.x = (u1.x >= 0.5f) ? v1.x * 2.f : 0.f;
        v1.y = fmaxf(acc1.y * inv + b1.y, 0.f); v1.y = (u1.y >= 0.5f) ? v1.y * 2.f : 0.f;
        v1.z = fmaxf(acc1.z * inv + b1.z, 0.f); v1.z = (u1.z >= 0.5f) ? v1.z * 2.f : 0.f;
        v1.w = fmaxf(acc1.w * inv + b1.w, 0.f); v1.w = (u1.w >= 0.5f) ? v1.w * 2.f : 0.f;

        float4* op = (float4*)(g_agg + (size_t)dst * D);
        op[lane] = v0; op[lane + 32] = v1;

        int c0 = lane * 4, c1 = 128 + lane * 4;
        atomicAdd(&s_sum[c0 + 0], v0.x); atomicAdd(&s_sq[c0 + 0], v0.x * v0.x);
        atomicAdd(&s_sum[c0 + 1], v0.y); atomicAdd(&s_sq[c0 + 1], v0.y * v0.y);
        atomicAdd(&s_sum[c0 + 2], v0.z); atomicAdd(&s_sq[c0 + 2], v0.z * v0.z);
        atomicAdd(&s_sum[c0 + 3], v0.w); atomicAdd(&s_sq[c0 + 3], v0.w * v0.w);
        atomicAdd(&s_sum[c1 + 0], v1.x); atomicAdd(&s_sq[c1 + 0], v1.x * v1.x);
        atomicAdd(&s_sum[c1 + 1], v1.y); atomicAdd(&s_sq[c1 + 1], v1.y * v1.y);
        atomicAdd(&s_sum[c1 + 2], v1.z); atomicAdd(&s_sq[c1 + 2], v1.z * v1.z);
        atomicAdd(&s_sum[c1 + 3], v1.w); atomicAdd(&s_sq[c1 + 3], v1.w * v1.w);
    }
    __syncthreads();
    atomicAdd(&g_colsum[tid], s_sum[tid]);
    atomicAdd(&g_colsumsq[tid], s_sq[tid]);
}

// ---------------- final BN normalize --------------------------------
__global__ void k_bnnorm(const float* __restrict__ gamma, const float* __restrict__ beta,
                         float* __restrict__ out, int N) {
    int d = threadIdx.x;
    float invN = 1.f / (float)N;
    float mean = g_colsum[d] * invN;
    float var = g_colsumsq[d] * invN - mean * mean;
    float inv = rsqrtf(var + 1e-5f);
    float ga = gamma[d], be = beta[d];
    for (int r = blockIdx.x; r < N; r += gridDim.x) {
        out[(size_t)r * D + d] = ga * (g_agg[(size_t)r * D + d] - mean) * inv + be;
    }
}

// ---------------- launch ---------------------------------------------
extern "C" void kernel_launch(void* const* d_in, const int* in_sizes, int n_in,
                              void* d_out, int out_size) {
    (void)n_in; (void)out_size;
    const float* x     = (const float*)d_in[0];
    const void*  ei    = d_in[1];
    const float* Wl    = (const float*)d_in[2];
    const float* bl    = (const float*)d_in[3];
    const float* Wr    = (const float*)d_in[4];
    const float* br    = (const float*)d_in[5];
    const float* att   = (const float*)d_in[6];
    const float* bias  = (const float*)d_in[7];
    const float* gamma = (const float*)d_in[8];
    const float* beta  = (const float*)d_in[9];
    const float* du    = (const float*)d_in[10];

    int N = in_sizes[0] / D;
    int E = in_sizes[1] / 2;
    int mrows = (N + 127) / 128;
    int NPAD = mrows * 128;

    const int SMEM_MMA = 2 * STG;   // 221184 bytes
    static cudaStream_t s2 = nullptr;
    static cudaEvent_t evFork = nullptr, evJoin = nullptr;
    if (!s2) {
        cudaFuncSetAttribute(k_hmma, cudaFuncAttributeMaxDynamicSharedMemorySize, SMEM_MMA);
        cudaStreamCreateWithFlags(&s2, cudaStreamNonBlocking);
        cudaEventCreateWithFlags(&evFork, cudaEventDisableTiming);
        cudaEventCreateWithFlags(&evJoin, cudaEventDisableTiming);
    }

    // ---- fork: CSR chain on s2, GEMM chain on main stream ----
    cudaEventRecord(evFork, 0);
    cudaStreamWaitEvent(s2, evFork, 0);

    // branch B (s2): init + dtype detect -> count -> alloc -> fill
    k_init<<<40, 256, 0, s2>>>((const long long*)ei, E, N);
    k_count<<<(E / 2 + 256) / 256, 256, 0, s2>>>(ei, E);
    k_alloc<<<(N + 255) / 256, 256, 0, s2>>>(N);
    k_fill<<<(E / 2 + 256) / 256, 256, 0, s2>>>(ei, E);
    cudaEventRecord(evJoin, s2);

    // branch A (main): bf16 conversions -> fused dual GEMM
    int convx_threads = NPAD * (D / 4);
    k_conv_x<<<(convx_threads + 255) / 256, 256>>>(x, N, NPAD);
    dim3 gw(16, 8);
    k_conv_w<<<gw, 256>>>(Wl, Wr);
    dim3 gg(2, mrows);
    k_hmma<<<gg, 512, SMEM_MMA>>>(bl, br, N);

    // ---- join ----
    cudaStreamWaitEvent(0, evJoin, 0);

    // dst-centric aggregation + epilogue + BN stats
    k_agg<<<(N + 7) / 8, 256>>>(att, bias, du, N);

    // BN normalize
    k_bnnorm<<<512, 256>>>(gamma, beta, (float*)d_out, N);
}